// round 1
// baseline (speedup 1.0000x reference)
#include <cuda_runtime.h>
#include <cstdint>

#define N_NODES  100000
#define N_EDGES  1600000
#define IN_CH    128
#define HID      256
#define OUT_CH   128
#define N_GRAPHS 2048

// ---------------- scratch (device globals: no allocation allowed) ----------------
__device__ int   g_deg[N_NODES];
__device__ int   g_fill[N_NODES];
__device__ int   g_rowptr[N_NODES + 1];
__device__ int   g_col[N_EDGES];
__device__ float g_agg[(size_t)N_NODES * HID];
__device__ float g_h1 [(size_t)N_NODES * HID];
__device__ float g_h2 [(size_t)N_NODES * HID];
__device__ float g_pool  [N_GRAPHS * HID];
__device__ float g_hidden[N_GRAPHS * HID];

// ---------------- packed f32x2 helpers ----------------
__device__ __forceinline__ void fma2(unsigned long long& c, unsigned long long a, unsigned long long b) {
    asm("fma.rn.f32x2 %0, %1, %2, %3;" : "=l"(c) : "l"(a), "l"(b), "l"(c));
}
__device__ __forceinline__ unsigned long long pk2(float lo, float hi) {
    unsigned long long r; asm("mov.b64 %0, {%1, %2};" : "=l"(r) : "f"(lo), "f"(hi)); return r;
}
__device__ __forceinline__ unsigned long long dup2(float x) {
    unsigned long long r; asm("mov.b64 %0, {%1, %1};" : "=l"(r) : "f"(x)); return r;
}
__device__ __forceinline__ float2 upk2(unsigned long long v) {
    float2 r; asm("mov.b64 {%0, %1}, %2;" : "=f"(r.x), "=f"(r.y) : "l"(v)); return r;
}

// ---------------- CSR build ----------------
__global__ void zero_kernel() {
    int i = blockIdx.x * blockDim.x + threadIdx.x;
    if (i < N_NODES) { g_deg[i] = 0; g_fill[i] = 0; }
}

__global__ void hist_kernel(const int* __restrict__ dst) {
    int e = blockIdx.x * blockDim.x + threadIdx.x;
    if (e < N_EDGES) atomicAdd(&g_deg[dst[e]], 1);
}

__global__ void scan_kernel() {
    __shared__ int part[1024];
    int t = threadIdx.x;
    const int CH = (N_NODES + 1023) / 1024;
    int s0 = t * CH;
    int s1 = s0 + CH; if (s1 > N_NODES) s1 = N_NODES;
    int sum = 0;
    for (int i = s0; i < s1; i++) sum += g_deg[i];
    part[t] = sum;
    __syncthreads();
    for (int off = 1; off < 1024; off <<= 1) {
        int v = (t >= off) ? part[t - off] : 0;
        __syncthreads();
        part[t] += v;
        __syncthreads();
    }
    int run = part[t] - sum;   // exclusive prefix
    for (int i = s0; i < s1; i++) { g_rowptr[i] = run; run += g_deg[i]; }
    if (t == 0) g_rowptr[N_NODES] = N_EDGES;
}

__global__ void scatter_kernel(const int* __restrict__ src, const int* __restrict__ dst) {
    int e = blockIdx.x * blockDim.x + threadIdx.x;
    if (e >= N_EDGES) return;
    int d = dst[e];
    int p = g_rowptr[d] + atomicAdd(&g_fill[d], 1);
    g_col[p] = src[e];
}

// ---------------- mean aggregation: one warp per node ----------------
template <int C>
__global__ void agg_kernel(const float* __restrict__ feat, float* __restrict__ outp) {
    int w = (blockIdx.x * blockDim.x + threadIdx.x) >> 5;
    int lane = threadIdx.x & 31;
    if (w >= N_NODES) return;
    int beg = g_rowptr[w], end = g_rowptr[w + 1];
    constexpr int V = C / 128;       // float4's per lane
    float4 acc[V];
#pragma unroll
    for (int v = 0; v < V; v++) acc[v] = make_float4(0.f, 0.f, 0.f, 0.f);
    for (int j = beg; j < end; j++) {
        int s = g_col[j];
        const float4* row = (const float4*)(feat + (size_t)s * C);
#pragma unroll
        for (int v = 0; v < V; v++) {
            float4 t = row[lane + 32 * v];
            acc[v].x += t.x; acc[v].y += t.y; acc[v].z += t.z; acc[v].w += t.w;
        }
    }
    float inv = (end > beg) ? 1.f / (float)(end - beg) : 0.f;
    float4* orow = (float4*)(outp + (size_t)w * C);
#pragma unroll
    for (int v = 0; v < V; v++) {
        acc[v].x *= inv; acc[v].y *= inv; acc[v].z *= inv; acc[v].w *= inv;
        orow[lane + 32 * v] = acc[v];
    }
}

// ---------------- fused dual-input GEMM: C = act([A1|A2] @ [B1;B2] + bias) ----------------
// 128x128 tile, BK=8, 256 threads, 8x8 micro-tile via packed f32x2 FMA.
__global__ __launch_bounds__(256, 2) void gemm_bias_act(
    const float* __restrict__ A1, int K1, const float* __restrict__ B1,
    const float* __restrict__ A2, int K2, const float* __restrict__ B2,
    const float* __restrict__ bias, float* __restrict__ Cc,
    int M, int Nout, int do_relu)
{
    __shared__ float As[8][132];   // padded: stride 528B = 16B-aligned, conflict-free
    __shared__ float Bs[8][128];

    int tid = threadIdx.x;
    int tx = tid & 15, ty = tid >> 4;
    int row0 = blockIdx.x * 128;
    int col0 = blockIdx.y * 128;

    unsigned long long acc[8][4];
#pragma unroll
    for (int i = 0; i < 8; i++)
#pragma unroll
        for (int j = 0; j < 4; j++) acc[i][j] = 0ull;

    int lm = tid >> 1;          // A-tile row 0..127
    int lk = (tid & 1) * 4;     // A-tile k offset 0 or 4
    int bk = tid >> 5;          // B-tile k row 0..7
    int bn = (tid & 31) * 4;    // B-tile col

#pragma unroll 1
    for (int seg = 0; seg < 2; seg++) {
        const float* A = seg ? A2 : A1;
        const float* B = seg ? B2 : B1;
        int K = seg ? K2 : K1;
        if (K == 0 || A == nullptr) continue;
#pragma unroll 1
        for (int k0 = 0; k0 < K; k0 += 8) {
            float4 av = make_float4(0.f, 0.f, 0.f, 0.f);
            int r = row0 + lm;
            if (r < M) av = *(const float4*)(A + (size_t)r * K + k0 + lk);
            float4 bv = *(const float4*)(B + (size_t)(k0 + bk) * Nout + col0 + bn);
            __syncthreads();
            As[lk + 0][lm] = av.x; As[lk + 1][lm] = av.y;
            As[lk + 2][lm] = av.z; As[lk + 3][lm] = av.w;
            *(float4*)&Bs[bk][bn] = bv;
            __syncthreads();
#pragma unroll
            for (int k = 0; k < 8; k++) {
                float4 a0 = *(const float4*)&As[k][ty * 4];
                float4 a1 = *(const float4*)&As[k][64 + ty * 4];
                float4 b0 = *(const float4*)&Bs[k][tx * 4];
                float4 b1 = *(const float4*)&Bs[k][64 + tx * 4];
                unsigned long long bp[4];
                bp[0] = pk2(b0.x, b0.y); bp[1] = pk2(b0.z, b0.w);
                bp[2] = pk2(b1.x, b1.y); bp[3] = pk2(b1.z, b1.w);
                float a[8] = {a0.x, a0.y, a0.z, a0.w, a1.x, a1.y, a1.z, a1.w};
#pragma unroll
                for (int i = 0; i < 8; i++) {
                    unsigned long long ai = dup2(a[i]);
                    fma2(acc[i][0], ai, bp[0]);
                    fma2(acc[i][1], ai, bp[1]);
                    fma2(acc[i][2], ai, bp[2]);
                    fma2(acc[i][3], ai, bp[3]);
                }
            }
        }
    }

    // epilogue: bias + optional relu
#pragma unroll
    for (int i = 0; i < 8; i++) {
        int r = row0 + ((i < 4) ? ty * 4 + i : 64 + ty * 4 + (i - 4));
        if (r >= M) continue;
#pragma unroll
        for (int j = 0; j < 4; j++) {
            int c = col0 + ((j < 2) ? tx * 4 + j * 2 : 64 + tx * 4 + (j - 2) * 2);
            float2 v = upk2(acc[i][j]);
            v.x += bias[c]; v.y += bias[c + 1];
            if (do_relu) { v.x = fmaxf(v.x, 0.f); v.y = fmaxf(v.y, 0.f); }
            *(float2*)(Cc + (size_t)r * Nout + c) = v;
        }
    }
}

// ---------------- global mean pool: one CTA per graph (batch is sorted) ----------------
__device__ __forceinline__ int lowerb(const int* __restrict__ a, int n, int key) {
    int lo = 0, hi = n;
    while (lo < hi) { int mid = (lo + hi) >> 1; if (a[mid] < key) lo = mid + 1; else hi = mid; }
    return lo;
}

__global__ void pool_kernel(const float* __restrict__ h, const int* __restrict__ batch,
                            float* __restrict__ pooled) {
    int g = blockIdx.x;
    int c = threadIdx.x;        // 256 channels
    __shared__ int s_lo, s_hi;
    if (c == 0) s_lo = lowerb(batch, N_NODES, g);
    if (c == 1) s_hi = lowerb(batch, N_NODES, g + 1);
    __syncthreads();
    int lo = s_lo, hi = s_hi;
    float s = 0.f;
    for (int r = lo; r < hi; r++) s += h[(size_t)r * HID + c];
    float inv = (hi > lo) ? 1.f / (float)(hi - lo) : 0.f;
    pooled[g * HID + c] = s * inv;
}

// ---------------- launch ----------------
extern "C" void kernel_launch(void* const* d_in, const int* in_sizes, int n_in,
                              void* d_out, int out_size) {
    const float* x   = (const float*)d_in[0];
    const int*   ei  = (const int*)d_in[1];
    const int*   src = ei;
    const int*   dst = ei + N_EDGES;
    const int* batch = (const int*)d_in[2];
    const float* W1l = (const float*)d_in[3];
    const float* b1  = (const float*)d_in[4];
    const float* W1r = (const float*)d_in[5];
    const float* W2l = (const float*)d_in[6];
    const float* b2  = (const float*)d_in[7];
    const float* W2r = (const float*)d_in[8];
    const float* W3  = (const float*)d_in[9];
    const float* b3  = (const float*)d_in[10];
    const float* W4  = (const float*)d_in[11];
    const float* b4  = (const float*)d_in[12];
    float* out = (float*)d_out;

    void *p_agg, *p_h1, *p_h2, *p_pool, *p_hidden;
    cudaGetSymbolAddress(&p_agg, g_agg);
    cudaGetSymbolAddress(&p_h1, g_h1);
    cudaGetSymbolAddress(&p_h2, g_h2);
    cudaGetSymbolAddress(&p_pool, g_pool);
    cudaGetSymbolAddress(&p_hidden, g_hidden);
    float* agg    = (float*)p_agg;
    float* h1     = (float*)p_h1;
    float* h2     = (float*)p_h2;
    float* pooled = (float*)p_pool;
    float* hidden = (float*)p_hidden;

    const int TB = 256;

    // CSR build (per call — edges are a runtime input)
    zero_kernel<<<(N_NODES + TB - 1) / TB, TB>>>();
    hist_kernel<<<(N_EDGES + TB - 1) / TB, TB>>>(dst);
    scan_kernel<<<1, 1024>>>();
    scatter_kernel<<<(N_EDGES + TB - 1) / TB, TB>>>(src, dst);

    // Layer 1: mean-aggregate x (128ch), then h1 = relu([agg|x] @ [W1l;W1r] + b1)
    agg_kernel<IN_CH><<<(N_NODES * 32 + TB - 1) / TB, TB>>>(x, agg);
    {
        dim3 grid((N_NODES + 127) / 128, HID / 128);
        gemm_bias_act<<<grid, 256>>>(agg, IN_CH, W1l, x, IN_CH, W1r, b1, h1,
                                     N_NODES, HID, 1);
    }

    // Layer 2: mean-aggregate h1 (256ch), then h2 = relu([agg|h1] @ [W2l;W2r] + b2)
    agg_kernel<HID><<<(N_NODES * 32 + TB - 1) / TB, TB>>>(h1, agg);
    {
        dim3 grid((N_NODES + 127) / 128, HID / 128);
        gemm_bias_act<<<grid, 256>>>(agg, HID, W2l, h1, HID, W2r, b2, h2,
                                     N_NODES, HID, 1);
    }

    // Global mean pool
    pool_kernel<<<N_GRAPHS, HID>>>(h2, batch, pooled);

    // MLP head
    {
        dim3 grid((N_GRAPHS + 127) / 128, HID / 128);
        gemm_bias_act<<<grid, 256>>>(pooled, HID, W3, nullptr, 0, nullptr, b3, hidden,
                                     N_GRAPHS, HID, 1);
    }
    {
        dim3 grid((N_GRAPHS + 127) / 128, OUT_CH / 128);
        gemm_bias_act<<<grid, 256>>>(hidden, HID, W4, nullptr, 0, nullptr, b4, out,
                                     N_GRAPHS, OUT_CH, 0);
    }
}

// round 3
// speedup vs baseline: 1.2654x; 1.2654x over previous
#include <cuda_runtime.h>
#include <cuda_bf16.h>
#include <cstdint>

#define N_NODES  100000
#define N_EDGES  1600000
#define IN_CH    128
#define HID      256
#define OUT_CH   128
#define N_GRAPHS 2048

// ---------------- scratch (device globals: no allocation allowed) ----------------
__device__ int   g_deg[N_NODES];
__device__ int   g_fill[N_NODES];
__device__ int   g_rowptr[N_NODES + 1];
__device__ int   g_col[N_EDGES];
__device__ float g_agg[(size_t)N_NODES * HID];
__device__ float g_h1 [(size_t)N_NODES * HID];
__device__ float g_h2 [(size_t)N_NODES * HID];
__device__ float g_pool  [N_GRAPHS * HID];
__device__ float g_hidden[N_GRAPHS * HID];

// ---------------- helpers ----------------
__device__ __forceinline__ uint16_t bf_hi_bits(float v, float& hf) {
    __nv_bfloat16 b = __float2bfloat16_rn(v);
    hf = __bfloat162float(b);
    return *(uint16_t*)&b;
}
__device__ __forceinline__ uint16_t bf_bits(float v) {
    __nv_bfloat16 b = __float2bfloat16_rn(v);
    return *(uint16_t*)&b;
}

// packed f32x2 helpers (head MLP GEMM)
__device__ __forceinline__ void fma2(unsigned long long& c, unsigned long long a, unsigned long long b) {
    asm("fma.rn.f32x2 %0, %1, %2, %3;" : "=l"(c) : "l"(a), "l"(b), "l"(c));
}
__device__ __forceinline__ unsigned long long pk2(float lo, float hi) {
    unsigned long long r; asm("mov.b64 %0, {%1, %2};" : "=l"(r) : "f"(lo), "f"(hi)); return r;
}
__device__ __forceinline__ unsigned long long dup2(float x) {
    unsigned long long r; asm("mov.b64 %0, {%1, %1};" : "=l"(r) : "f"(x)); return r;
}
__device__ __forceinline__ float2 upk2(unsigned long long v) {
    float2 r; asm("mov.b64 {%0, %1}, %2;" : "=f"(r.x), "=f"(r.y) : "l"(v)); return r;
}

// ---------------- CSR build ----------------
__global__ void zero_kernel() {
    int i = blockIdx.x * blockDim.x + threadIdx.x;
    if (i < N_NODES) { g_deg[i] = 0; g_fill[i] = 0; }
}
__global__ void hist_kernel(const int* __restrict__ dst) {
    int e = blockIdx.x * blockDim.x + threadIdx.x;
    if (e < N_EDGES) atomicAdd(&g_deg[dst[e]], 1);
}
__global__ void scan_kernel() {
    __shared__ int part[1024];
    int t = threadIdx.x;
    const int CH = (N_NODES + 1023) / 1024;
    int s0 = t * CH, s1 = s0 + CH; if (s1 > N_NODES) s1 = N_NODES;
    int sum = 0;
    for (int i = s0; i < s1; i++) sum += g_deg[i];
    part[t] = sum;
    __syncthreads();
    for (int off = 1; off < 1024; off <<= 1) {
        int v = (t >= off) ? part[t - off] : 0;
        __syncthreads();
        part[t] += v;
        __syncthreads();
    }
    int run = part[t] - sum;
    for (int i = s0; i < s1; i++) { g_rowptr[i] = run; run += g_deg[i]; }
    if (t == 0) g_rowptr[N_NODES] = N_EDGES;
}
__global__ void scatter_kernel(const int* __restrict__ src, const int* __restrict__ dst) {
    int e = blockIdx.x * blockDim.x + threadIdx.x;
    if (e >= N_EDGES) return;
    int d = dst[e];
    int p = g_rowptr[d] + atomicAdd(&g_fill[d], 1);
    g_col[p] = src[e];
}

// ---------------- mean aggregation: one warp per node ----------------
template <int C>
__global__ void agg_kernel(const float* __restrict__ feat, float* __restrict__ outp) {
    int w = (blockIdx.x * blockDim.x + threadIdx.x) >> 5;
    int lane = threadIdx.x & 31;
    if (w >= N_NODES) return;
    int beg = g_rowptr[w], end = g_rowptr[w + 1];
    constexpr int V = C / 128;
    float4 acc[V];
#pragma unroll
    for (int v = 0; v < V; v++) acc[v] = make_float4(0.f, 0.f, 0.f, 0.f);
    for (int j = beg; j < end; j++) {
        int s = g_col[j];
        const float4* row = (const float4*)(feat + (size_t)s * C);
#pragma unroll
        for (int v = 0; v < V; v++) {
            float4 t = row[lane + 32 * v];
            acc[v].x += t.x; acc[v].y += t.y; acc[v].z += t.z; acc[v].w += t.w;
        }
    }
    float inv = (end > beg) ? 1.f / (float)(end - beg) : 0.f;
    float4* orow = (float4*)(outp + (size_t)w * C);
#pragma unroll
    for (int v = 0; v < V; v++) {
        acc[v].x *= inv; acc[v].y *= inv; acc[v].z *= inv; acc[v].w *= inv;
        orow[lane + 32 * v] = acc[v];
    }
}

// ---------------- bf16-split HMMA GEMM ----------------
// C[M,256] = relu?( [A1|A2] @ [B1;B2] + bias ),  fp32 in/out.
// 3-pass split: Ahi*Bhi + Alo*Bhi + Ahi*Blo, fp32 accum (mma.sync m16n8k16).
// CTA tile 128x128 (grid.y=2 for N=256). BK=32. 8 warps = 4(m) x 2(n), warp tile 32x64.

#define LDB_S 40   // smem row stride in bf16 elems (80B: bank-disjoint frag loads)

__device__ __forceinline__ void mma_bf16(float* c, const uint32_t* a, const uint32_t* b) {
    asm volatile(
        "mma.sync.aligned.m16n8k16.row.col.f32.bf16.bf16.f32 "
        "{%0,%1,%2,%3}, {%4,%5,%6,%7}, {%8,%9}, {%0,%1,%2,%3};"
        : "+f"(c[0]), "+f"(c[1]), "+f"(c[2]), "+f"(c[3])
        : "r"(a[0]), "r"(a[1]), "r"(a[2]), "r"(a[3]), "r"(b[0]), "r"(b[1]));
}

__global__ __launch_bounds__(256, 1) void hgemm_kernel(
    const float* __restrict__ A1, int K1, const float* __restrict__ B1,
    const float* __restrict__ A2, int K2, const float* __restrict__ B2,
    const float* __restrict__ bias, float* __restrict__ Cc,
    int M, int do_relu)
{
    __shared__ __align__(16) uint16_t As_h[128 * LDB_S];
    __shared__ __align__(16) uint16_t As_l[128 * LDB_S];
    __shared__ __align__(16) uint16_t Bs_h[128 * LDB_S];
    __shared__ __align__(16) uint16_t Bs_l[128 * LDB_S];

    const int tid = threadIdx.x;
    const int lane = tid & 31, wid = tid >> 5;
    const int wm = wid & 3, wn = wid >> 2;          // 4 x 2 warp grid
    const int g = lane >> 2, th = lane & 3;
    const int row0 = blockIdx.x * 128;
    const int n0 = blockIdx.y * 128;

    const int half1 = K1 >> 5;
    const int nch = half1 + (K2 >> 5);

    float acc[2][8][4];
#pragma unroll
    for (int mt = 0; mt < 2; mt++)
#pragma unroll
        for (int nt = 0; nt < 8; nt++)
#pragma unroll
            for (int r = 0; r < 4; r++) acc[mt][nt][r] = 0.f;

    float4 va[4];
    float  vb[4][4];

    // ---- prefetch chunk 0 ----
    {
        const float* Aseg = A1; const float* Bseg = B1; int ldA = K1, kloc = 0;
#pragma unroll
        for (int i = 0; i < 4; i++) {
            int idx = tid + i * 256;
            int r = idx >> 3, q = idx & 7;
            va[i] = (row0 + r < M)
                ? *(const float4*)(Aseg + (size_t)(row0 + r) * ldA + kloc + q * 4)
                : make_float4(0.f, 0.f, 0.f, 0.f);
        }
#pragma unroll
        for (int i = 0; i < 4; i++) {
            int idx = tid + i * 256;
            int n = idx & 127, kq = idx >> 7;
#pragma unroll
            for (int j = 0; j < 4; j++)
                vb[i][j] = Bseg[(size_t)(kloc + kq * 4 + j) * 256 + n0 + n];
        }
    }

#pragma unroll 1
    for (int c = 0; c < nch; c++) {
        // ---- store prefetched chunk to smem (convert + split) ----
#pragma unroll
        for (int i = 0; i < 4; i++) {
            int idx = tid + i * 256;
            int r = idx >> 3, q = idx & 7;
            float f[4] = {va[i].x, va[i].y, va[i].z, va[i].w};
            uint16_t h[4], l[4];
#pragma unroll
            for (int j = 0; j < 4; j++) {
                float hf; h[j] = bf_hi_bits(f[j], hf); l[j] = bf_bits(f[j] - hf);
            }
            uint2 ph = make_uint2((uint32_t)h[0] | ((uint32_t)h[1] << 16),
                                  (uint32_t)h[2] | ((uint32_t)h[3] << 16));
            uint2 pl = make_uint2((uint32_t)l[0] | ((uint32_t)l[1] << 16),
                                  (uint32_t)l[2] | ((uint32_t)l[3] << 16));
            *(uint2*)&As_h[r * LDB_S + q * 4] = ph;
            *(uint2*)&As_l[r * LDB_S + q * 4] = pl;
        }
#pragma unroll
        for (int i = 0; i < 4; i++) {
            int idx = tid + i * 256;
            int n = idx & 127, kq = idx >> 7;
            uint16_t h[4], l[4];
#pragma unroll
            for (int j = 0; j < 4; j++) {
                float hf; h[j] = bf_hi_bits(vb[i][j], hf); l[j] = bf_bits(vb[i][j] - hf);
            }
            uint2 ph = make_uint2((uint32_t)h[0] | ((uint32_t)h[1] << 16),
                                  (uint32_t)h[2] | ((uint32_t)h[3] << 16));
            uint2 pl = make_uint2((uint32_t)l[0] | ((uint32_t)l[1] << 16),
                                  (uint32_t)l[2] | ((uint32_t)l[3] << 16));
            *(uint2*)&Bs_h[n * LDB_S + kq * 4] = ph;
            *(uint2*)&Bs_l[n * LDB_S + kq * 4] = pl;
        }
        __syncthreads();

        // ---- prefetch next chunk ----
        if (c + 1 < nch) {
            int cn = c + 1;
            const float* Aseg; const float* Bseg; int ldA, kloc;
            if (cn < half1) { Aseg = A1; Bseg = B1; ldA = K1; kloc = cn * 32; }
            else            { Aseg = A2; Bseg = B2; ldA = K2; kloc = (cn - half1) * 32; }
#pragma unroll
            for (int i = 0; i < 4; i++) {
                int idx = tid + i * 256;
                int r = idx >> 3, q = idx & 7;
                va[i] = (row0 + r < M)
                    ? *(const float4*)(Aseg + (size_t)(row0 + r) * ldA + kloc + q * 4)
                    : make_float4(0.f, 0.f, 0.f, 0.f);
            }
#pragma unroll
            for (int i = 0; i < 4; i++) {
                int idx = tid + i * 256;
                int n = idx & 127, kq = idx >> 7;
#pragma unroll
                for (int j = 0; j < 4; j++)
                    vb[i][j] = Bseg[(size_t)(kloc + kq * 4 + j) * 256 + n0 + n];
            }
        }

        // ---- compute: 2 k16 steps x 3 passes ----
#pragma unroll
        for (int step = 0; step < 2; step++) {
            const int kofs = step * 16 + 2 * th;
            uint32_t ah[2][4], al[2][4], bh[8][2], bl[8][2];
#pragma unroll
            for (int mt = 0; mt < 2; mt++) {
                int rb = (wm * 32 + mt * 16 + g) * LDB_S;
                ah[mt][0] = *(const uint32_t*)&As_h[rb + kofs];
                ah[mt][1] = *(const uint32_t*)&As_h[rb + 8 * LDB_S + kofs];
                ah[mt][2] = *(const uint32_t*)&As_h[rb + kofs + 8];
                ah[mt][3] = *(const uint32_t*)&As_h[rb + 8 * LDB_S + kofs + 8];
            }
#pragma unroll
            for (int nt = 0; nt < 8; nt++) {
                int rb = (wn * 64 + nt * 8 + g) * LDB_S;
                bh[nt][0] = *(const uint32_t*)&Bs_h[rb + kofs];
                bh[nt][1] = *(const uint32_t*)&Bs_h[rb + kofs + 8];
            }
#pragma unroll
            for (int mt = 0; mt < 2; mt++)
#pragma unroll
                for (int nt = 0; nt < 8; nt++) mma_bf16(acc[mt][nt], ah[mt], bh[nt]);

#pragma unroll
            for (int mt = 0; mt < 2; mt++) {
                int rb = (wm * 32 + mt * 16 + g) * LDB_S;
                al[mt][0] = *(const uint32_t*)&As_l[rb + kofs];
                al[mt][1] = *(const uint32_t*)&As_l[rb + 8 * LDB_S + kofs];
                al[mt][2] = *(const uint32_t*)&As_l[rb + kofs + 8];
                al[mt][3] = *(const uint32_t*)&As_l[rb + 8 * LDB_S + kofs + 8];
            }
#pragma unroll
            for (int mt = 0; mt < 2; mt++)
#pragma unroll
                for (int nt = 0; nt < 8; nt++) mma_bf16(acc[mt][nt], al[mt], bh[nt]);

#pragma unroll
            for (int nt = 0; nt < 8; nt++) {
                int rb = (wn * 64 + nt * 8 + g) * LDB_S;
                bl[nt][0] = *(const uint32_t*)&Bs_l[rb + kofs];
                bl[nt][1] = *(const uint32_t*)&Bs_l[rb + kofs + 8];
            }
#pragma unroll
            for (int mt = 0; mt < 2; mt++)
#pragma unroll
                for (int nt = 0; nt < 8; nt++) mma_bf16(acc[mt][nt], ah[mt], bl[nt]);
        }
        __syncthreads();
    }

    // ---- epilogue: bias + relu ----
#pragma unroll
    for (int mt = 0; mt < 2; mt++) {
        int rbase = row0 + wm * 32 + mt * 16 + g;
#pragma unroll
        for (int nt = 0; nt < 8; nt++) {
            int col = n0 + wn * 64 + nt * 8 + th * 2;
            float bx = bias[col], by = bias[col + 1];
            float2 v0 = make_float2(acc[mt][nt][0] + bx, acc[mt][nt][1] + by);
            float2 v1 = make_float2(acc[mt][nt][2] + bx, acc[mt][nt][3] + by);
            if (do_relu) {
                v0.x = fmaxf(v0.x, 0.f); v0.y = fmaxf(v0.y, 0.f);
                v1.x = fmaxf(v1.x, 0.f); v1.y = fmaxf(v1.y, 0.f);
            }
            if (rbase < M)     *(float2*)(Cc + (size_t)rbase * 256 + col) = v0;
            if (rbase + 8 < M) *(float2*)(Cc + (size_t)(rbase + 8) * 256 + col) = v1;
        }
    }
}

// ---------------- fp32 GEMM (head MLP only; small) ----------------
__global__ __launch_bounds__(256, 2) void gemm_bias_act(
    const float* __restrict__ A1, int K1, const float* __restrict__ B1,
    const float* __restrict__ bias, float* __restrict__ Cc,
    int M, int Nout, int do_relu)
{
    __shared__ float As[8][132];
    __shared__ float Bs[8][128];
    int tid = threadIdx.x;
    int tx = tid & 15, ty = tid >> 4;
    int row0 = blockIdx.x * 128;
    int col0 = blockIdx.y * 128;

    unsigned long long acc[8][4];
#pragma unroll
    for (int i = 0; i < 8; i++)
#pragma unroll
        for (int j = 0; j < 4; j++) acc[i][j] = 0ull;

    int lm = tid >> 1, lk = (tid & 1) * 4;
    int bk = tid >> 5, bn = (tid & 31) * 4;

#pragma unroll 1
    for (int k0 = 0; k0 < K1; k0 += 8) {
        float4 av = make_float4(0.f, 0.f, 0.f, 0.f);
        int r = row0 + lm;
        if (r < M) av = *(const float4*)(A1 + (size_t)r * K1 + k0 + lk);
        float4 bv = *(const float4*)(B1 + (size_t)(k0 + bk) * Nout + col0 + bn);
        __syncthreads();
        As[lk + 0][lm] = av.x; As[lk + 1][lm] = av.y;
        As[lk + 2][lm] = av.z; As[lk + 3][lm] = av.w;
        *(float4*)&Bs[bk][bn] = bv;
        __syncthreads();
#pragma unroll
        for (int k = 0; k < 8; k++) {
            float4 a0 = *(const float4*)&As[k][ty * 4];
            float4 a1 = *(const float4*)&As[k][64 + ty * 4];
            float4 b0 = *(const float4*)&Bs[k][tx * 4];
            float4 b1 = *(const float4*)&Bs[k][64 + tx * 4];
            unsigned long long bp[4];
            bp[0] = pk2(b0.x, b0.y); bp[1] = pk2(b0.z, b0.w);
            bp[2] = pk2(b1.x, b1.y); bp[3] = pk2(b1.z, b1.w);
            float a[8] = {a0.x, a0.y, a0.z, a0.w, a1.x, a1.y, a1.z, a1.w};
#pragma unroll
            for (int i = 0; i < 8; i++) {
                unsigned long long ai = dup2(a[i]);
                fma2(acc[i][0], ai, bp[0]);
                fma2(acc[i][1], ai, bp[1]);
                fma2(acc[i][2], ai, bp[2]);
                fma2(acc[i][3], ai, bp[3]);
            }
        }
    }
#pragma unroll
    for (int i = 0; i < 8; i++) {
        int r = row0 + ((i < 4) ? ty * 4 + i : 64 + ty * 4 + (i - 4));
        if (r >= M) continue;
#pragma unroll
        for (int j = 0; j < 4; j++) {
            int c = col0 + ((j < 2) ? tx * 4 + j * 2 : 64 + tx * 4 + (j - 2) * 2);
            float2 v = upk2(acc[i][j]);
            v.x += bias[c]; v.y += bias[c + 1];
            if (do_relu) { v.x = fmaxf(v.x, 0.f); v.y = fmaxf(v.y, 0.f); }
            *(float2*)(Cc + (size_t)r * Nout + c) = v;
        }
    }
}

// ---------------- global mean pool ----------------
__device__ __forceinline__ int lowerb(const int* __restrict__ a, int n, int key) {
    int lo = 0, hi = n;
    while (lo < hi) { int mid = (lo + hi) >> 1; if (a[mid] < key) lo = mid + 1; else hi = mid; }
    return lo;
}
__global__ void pool_kernel(const float* __restrict__ h, const int* __restrict__ batch,
                            float* __restrict__ pooled) {
    int g = blockIdx.x;
    int c = threadIdx.x;
    __shared__ int s_lo, s_hi;
    if (c == 0) s_lo = lowerb(batch, N_NODES, g);
    if (c == 1) s_hi = lowerb(batch, N_NODES, g + 1);
    __syncthreads();
    int lo = s_lo, hi = s_hi;
    float s = 0.f;
    for (int r = lo; r < hi; r++) s += h[(size_t)r * HID + c];
    float inv = (hi > lo) ? 1.f / (float)(hi - lo) : 0.f;
    pooled[g * HID + c] = s * inv;
}

// ---------------- launch ----------------
extern "C" void kernel_launch(void* const* d_in, const int* in_sizes, int n_in,
                              void* d_out, int out_size) {
    const float* x   = (const float*)d_in[0];
    const int*   ei  = (const int*)d_in[1];
    const int*   src = ei;
    const int*   dst = ei + N_EDGES;
    const int* batch = (const int*)d_in[2];
    const float* W1l = (const float*)d_in[3];
    const float* b1  = (const float*)d_in[4];
    const float* W1r = (const float*)d_in[5];
    const float* W2l = (const float*)d_in[6];
    const float* b2  = (const float*)d_in[7];
    const float* W2r = (const float*)d_in[8];
    const float* W3  = (const float*)d_in[9];
    const float* b3  = (const float*)d_in[10];
    const float* W4  = (const float*)d_in[11];
    const float* b4  = (const float*)d_in[12];
    float* out = (float*)d_out;

    void *p_agg, *p_h1, *p_h2, *p_pool, *p_hidden;
    cudaGetSymbolAddress(&p_agg, g_agg);
    cudaGetSymbolAddress(&p_h1, g_h1);
    cudaGetSymbolAddress(&p_h2, g_h2);
    cudaGetSymbolAddress(&p_pool, g_pool);
    cudaGetSymbolAddress(&p_hidden, g_hidden);
    float* agg    = (float*)p_agg;
    float* h1     = (float*)p_h1;
    float* h2     = (float*)p_h2;
    float* pooled = (float*)p_pool;
    float* hidden = (float*)p_hidden;

    const int TB = 256;
    const dim3 ggrid((N_NODES + 127) / 128, 2);

    // CSR build
    zero_kernel<<<(N_NODES + TB - 1) / TB, TB>>>();
    hist_kernel<<<(N_EDGES + TB - 1) / TB, TB>>>(dst);
    scan_kernel<<<1, 1024>>>();
    scatter_kernel<<<(N_EDGES + TB - 1) / TB, TB>>>(src, dst);

    // Layer 1: h1 = relu([mean-agg(x) | x] @ [W1l;W1r] + b1)
    agg_kernel<IN_CH><<<(N_NODES * 32 + TB - 1) / TB, TB>>>(x, agg);
    hgemm_kernel<<<ggrid, 256>>>(agg, IN_CH, W1l, x, IN_CH, W1r, b1, h1, N_NODES, 1);

    // Layer 2: h2 = relu([mean-agg(h1) | h1] @ [W2l;W2r] + b2)
    agg_kernel<HID><<<(N_NODES * 32 + TB - 1) / TB, TB>>>(h1, agg);
    hgemm_kernel<<<ggrid, 256>>>(agg, HID, W2l, h1, HID, W2r, b2, h2, N_NODES, 1);

    // Pool + MLP head (fp32)
    pool_kernel<<<N_GRAPHS, HID>>>(h2, batch, pooled);
    {
        dim3 grid((N_GRAPHS + 127) / 128, HID / 128);
        gemm_bias_act<<<grid, 256>>>(pooled, HID, W3, b3, hidden, N_GRAPHS, HID, 1);
    }
    {
        dim3 grid((N_GRAPHS + 127) / 128, OUT_CH / 128);
        gemm_bias_act<<<grid, 256>>>(hidden, HID, W4, b4, out, N_GRAPHS, OUT_CH, 0);
    }
}

// round 4
// speedup vs baseline: 1.3148x; 1.0391x over previous
#include <cuda_runtime.h>
#include <cuda_bf16.h>
#include <cstdint>

#define N_NODES  100000
#define N_EDGES  1600000
#define IN_CH    128
#define HID      256
#define OUT_CH   128
#define N_GRAPHS 2048

// ---------------- scratch (device globals: no allocation allowed) ----------------
__device__ int   g_deg[N_NODES];
__device__ int   g_fill[N_NODES];
__device__ int   g_rowptr[N_NODES + 1];
__device__ int   g_col[N_EDGES];
__device__ float g_agg[(size_t)N_NODES * HID];
__device__ float g_h1 [(size_t)N_NODES * HID];
__device__ float g_h2 [(size_t)N_NODES * HID];
__device__ float g_pool  [N_GRAPHS * HID];
__device__ float g_hidden[N_GRAPHS * HID];

// ---------------- helpers ----------------
__device__ __forceinline__ uint16_t bf_hi_bits(float v, float& hf) {
    __nv_bfloat16 b = __float2bfloat16_rn(v);
    hf = __bfloat162float(b);
    return *(uint16_t*)&b;
}
__device__ __forceinline__ uint16_t bf_bits(float v) {
    __nv_bfloat16 b = __float2bfloat16_rn(v);
    return *(uint16_t*)&b;
}
__device__ __forceinline__ uint32_t smem_u32(const void* p) {
    uint32_t a;
    asm("{ .reg .u64 t; cvta.to.shared.u64 t, %1; cvt.u32.u64 %0, t; }" : "=r"(a) : "l"(p));
    return a;
}

// packed f32x2 helpers (head MLP GEMM)
__device__ __forceinline__ void fma2(unsigned long long& c, unsigned long long a, unsigned long long b) {
    asm("fma.rn.f32x2 %0, %1, %2, %3;" : "=l"(c) : "l"(a), "l"(b), "l"(c));
}
__device__ __forceinline__ unsigned long long pk2(float lo, float hi) {
    unsigned long long r; asm("mov.b64 %0, {%1, %2};" : "=l"(r) : "f"(lo), "f"(hi)); return r;
}
__device__ __forceinline__ unsigned long long dup2(float x) {
    unsigned long long r; asm("mov.b64 %0, {%1, %1};" : "=l"(r) : "f"(x)); return r;
}
__device__ __forceinline__ float2 upk2(unsigned long long v) {
    float2 r; asm("mov.b64 {%0, %1}, %2;" : "=f"(r.x), "=f"(r.y) : "l"(v)); return r;
}

// ---------------- CSR build ----------------
__global__ void zero_kernel() {
    int i = blockIdx.x * blockDim.x + threadIdx.x;
    if (i < N_NODES) { g_deg[i] = 0; g_fill[i] = 0; }
}
__global__ void hist_kernel(const int* __restrict__ dst) {
    int e = blockIdx.x * blockDim.x + threadIdx.x;
    if (e < N_EDGES) atomicAdd(&g_deg[dst[e]], 1);
}
__global__ void scan_kernel() {
    __shared__ int part[1024];
    int t = threadIdx.x;
    const int CH = (N_NODES + 1023) / 1024;
    int s0 = t * CH, s1 = s0 + CH; if (s1 > N_NODES) s1 = N_NODES;
    int sum = 0;
    for (int i = s0; i < s1; i++) sum += g_deg[i];
    part[t] = sum;
    __syncthreads();
    for (int off = 1; off < 1024; off <<= 1) {
        int v = (t >= off) ? part[t - off] : 0;
        __syncthreads();
        part[t] += v;
        __syncthreads();
    }
    int run = part[t] - sum;
    for (int i = s0; i < s1; i++) { g_rowptr[i] = run; run += g_deg[i]; }
    if (t == 0) g_rowptr[N_NODES] = N_EDGES;
}
__global__ void scatter_kernel(const int* __restrict__ src, const int* __restrict__ dst) {
    int e = blockIdx.x * blockDim.x + threadIdx.x;
    if (e >= N_EDGES) return;
    int d = dst[e];
    int p = g_rowptr[d] + atomicAdd(&g_fill[d], 1);
    g_col[p] = src[e];
}

// ---------------- mean aggregation: one warp per node ----------------
template <int C>
__global__ void agg_kernel(const float* __restrict__ feat, float* __restrict__ outp) {
    int w = (blockIdx.x * blockDim.x + threadIdx.x) >> 5;
    int lane = threadIdx.x & 31;
    if (w >= N_NODES) return;
    int beg = g_rowptr[w], end = g_rowptr[w + 1];
    constexpr int V = C / 128;
    float4 acc[V];
#pragma unroll
    for (int v = 0; v < V; v++) acc[v] = make_float4(0.f, 0.f, 0.f, 0.f);
    for (int j = beg; j < end; j++) {
        int s = g_col[j];
        const float4* row = (const float4*)(feat + (size_t)s * C);
#pragma unroll
        for (int v = 0; v < V; v++) {
            float4 t = row[lane + 32 * v];
            acc[v].x += t.x; acc[v].y += t.y; acc[v].z += t.z; acc[v].w += t.w;
        }
    }
    float inv = (end > beg) ? 1.f / (float)(end - beg) : 0.f;
    float4* orow = (float4*)(outp + (size_t)w * C);
#pragma unroll
    for (int v = 0; v < V; v++) {
        acc[v].x *= inv; acc[v].y *= inv; acc[v].z *= inv; acc[v].w *= inv;
        orow[lane + 32 * v] = acc[v];
    }
}

// ---------------- bf16-split HMMA GEMM (ldmatrix edition) ----------------
// C[M,256] = relu?( [A1|A2] @ [B1;B2] + bias ),  fp32 in/out.
// 3-pass split: Ahi*Bhi + Alo*Bhi + Ahi*Blo, fp32 accum (mma.sync m16n8k16).
// CTA tile 128x128 (grid.y=2). BK=32. 8 warps = 4(m) x 2(n), warp tile 32x64.

#define LDB_S 40   // smem row stride in bf16 elems (80B): ldmatrix conflict-free

__device__ __forceinline__ void mma_bf16(float* c, const uint32_t* a, const uint32_t* b) {
    asm volatile(
        "mma.sync.aligned.m16n8k16.row.col.f32.bf16.bf16.f32 "
        "{%0,%1,%2,%3}, {%4,%5,%6,%7}, {%8,%9}, {%0,%1,%2,%3};"
        : "+f"(c[0]), "+f"(c[1]), "+f"(c[2]), "+f"(c[3])
        : "r"(a[0]), "r"(a[1]), "r"(a[2]), "r"(a[3]), "r"(b[0]), "r"(b[1]));
}
__device__ __forceinline__ void ldsm_x4(uint32_t* r, uint32_t addr) {
    asm volatile("ldmatrix.sync.aligned.m8n8.x4.shared.b16 {%0,%1,%2,%3}, [%4];"
                 : "=r"(r[0]), "=r"(r[1]), "=r"(r[2]), "=r"(r[3]) : "r"(addr));
}

__global__ __launch_bounds__(256, 1) void hgemm_kernel(
    const float* __restrict__ A1, int K1, const float* __restrict__ B1,
    const float* __restrict__ A2, int K2, const float* __restrict__ B2,
    const float* __restrict__ bias, float* __restrict__ Cc,
    int M, int do_relu)
{
    __shared__ __align__(16) uint16_t As_h[128 * LDB_S];
    __shared__ __align__(16) uint16_t As_l[128 * LDB_S];
    __shared__ __align__(16) uint16_t Bs_h[128 * LDB_S];
    __shared__ __align__(16) uint16_t Bs_l[128 * LDB_S];

    const int tid = threadIdx.x;
    const int lane = tid & 31, wid = tid >> 5;
    const int wm = wid & 3, wn = wid >> 2;          // 4 x 2 warp grid
    const int g = lane >> 2, th = lane & 3;
    const int row0 = blockIdx.x * 128;
    const int n0 = blockIdx.y * 128;

    const uint32_t sAh = smem_u32(As_h), sAl = smem_u32(As_l);
    const uint32_t sBh = smem_u32(Bs_h), sBl = smem_u32(Bs_l);

    const int half1 = K1 >> 5;
    const int nch = half1 + (K2 >> 5);

    float acc[2][8][4];
#pragma unroll
    for (int mt = 0; mt < 2; mt++)
#pragma unroll
        for (int nt = 0; nt < 8; nt++)
#pragma unroll
            for (int r = 0; r < 4; r++) acc[mt][nt][r] = 0.f;

    float4 va[4];
    float  vb[4][4];

    // ldmatrix per-lane address components
    const int lt = lane >> 3, lr = lane & 7;     // tile index (0..3), row in tile

    // ---- prefetch chunk 0 ----
    {
        const float* Aseg = A1; const float* Bseg = B1; int ldA = K1, kloc = 0;
#pragma unroll
        for (int i = 0; i < 4; i++) {
            int idx = tid + i * 256;
            int r = idx >> 3, q = idx & 7;
            va[i] = (row0 + r < M)
                ? *(const float4*)(Aseg + (size_t)(row0 + r) * ldA + kloc + q * 4)
                : make_float4(0.f, 0.f, 0.f, 0.f);
        }
#pragma unroll
        for (int i = 0; i < 4; i++) {
            int idx = tid + i * 256;
            int n = idx & 127, kq = idx >> 7;
#pragma unroll
            for (int j = 0; j < 4; j++)
                vb[i][j] = Bseg[(size_t)(kloc + kq * 4 + j) * 256 + n0 + n];
        }
    }

#pragma unroll 1
    for (int c = 0; c < nch; c++) {
        // ---- store prefetched chunk to smem (convert + split) ----
#pragma unroll
        for (int i = 0; i < 4; i++) {
            int idx = tid + i * 256;
            int r = idx >> 3, q = idx & 7;
            float f[4] = {va[i].x, va[i].y, va[i].z, va[i].w};
            uint16_t h[4], l[4];
#pragma unroll
            for (int j = 0; j < 4; j++) {
                float hf; h[j] = bf_hi_bits(f[j], hf); l[j] = bf_bits(f[j] - hf);
            }
            uint2 ph = make_uint2((uint32_t)h[0] | ((uint32_t)h[1] << 16),
                                  (uint32_t)h[2] | ((uint32_t)h[3] << 16));
            uint2 pl = make_uint2((uint32_t)l[0] | ((uint32_t)l[1] << 16),
                                  (uint32_t)l[2] | ((uint32_t)l[3] << 16));
            *(uint2*)&As_h[r * LDB_S + q * 4] = ph;
            *(uint2*)&As_l[r * LDB_S + q * 4] = pl;
        }
#pragma unroll
        for (int i = 0; i < 4; i++) {
            int idx = tid + i * 256;
            int n = idx & 127, kq = idx >> 7;
            uint16_t h[4], l[4];
#pragma unroll
            for (int j = 0; j < 4; j++) {
                float hf; h[j] = bf_hi_bits(vb[i][j], hf); l[j] = bf_bits(vb[i][j] - hf);
            }
            uint2 ph = make_uint2((uint32_t)h[0] | ((uint32_t)h[1] << 16),
                                  (uint32_t)h[2] | ((uint32_t)h[3] << 16));
            uint2 pl = make_uint2((uint32_t)l[0] | ((uint32_t)l[1] << 16),
                                  (uint32_t)l[2] | ((uint32_t)l[3] << 16));
            *(uint2*)&Bs_h[n * LDB_S + kq * 4] = ph;
            *(uint2*)&Bs_l[n * LDB_S + kq * 4] = pl;
        }
        __syncthreads();

        // ---- prefetch next chunk ----
        if (c + 1 < nch) {
            int cn = c + 1;
            const float* Aseg; const float* Bseg; int ldA, kloc;
            if (cn < half1) { Aseg = A1; Bseg = B1; ldA = K1; kloc = cn * 32; }
            else            { Aseg = A2; Bseg = B2; ldA = K2; kloc = (cn - half1) * 32; }
#pragma unroll
            for (int i = 0; i < 4; i++) {
                int idx = tid + i * 256;
                int r = idx >> 3, q = idx & 7;
                va[i] = (row0 + r < M)
                    ? *(const float4*)(Aseg + (size_t)(row0 + r) * ldA + kloc + q * 4)
                    : make_float4(0.f, 0.f, 0.f, 0.f);
            }
#pragma unroll
            for (int i = 0; i < 4; i++) {
                int idx = tid + i * 256;
                int n = idx & 127, kq = idx >> 7;
#pragma unroll
                for (int j = 0; j < 4; j++)
                    vb[i][j] = Bseg[(size_t)(kloc + kq * 4 + j) * 256 + n0 + n];
            }
        }

        // ---- compute: 2 k16 steps x 3 passes, ldmatrix fragment loads ----
#pragma unroll
        for (int step = 0; step < 2; step++) {
            const int k0 = step * 16;
            // A tiles: tile order a0=(m,k0) a1=(m+8,k0) a2=(m,k0+8) a3=(m+8,k0+8)
            uint32_t aoff[2];
#pragma unroll
            for (int mt = 0; mt < 2; mt++) {
                int ar = wm * 32 + mt * 16 + (lt & 1) * 8 + lr;
                int ak = k0 + (lt >> 1) * 8;
                aoff[mt] = (uint32_t)(ar * LDB_S + ak) * 2;
            }
            // B tiles (x4 covers two adjacent n-tiles):
            // tile order: b0(ntp*2)=(n,k0) b1(ntp*2)=(n,k0+8) then nt+1 pair
            uint32_t boff[4];
#pragma unroll
            for (int ntp = 0; ntp < 4; ntp++) {
                int nr = wn * 64 + ntp * 16 + (lt >> 1) * 8 + lr;
                int nk = k0 + (lt & 1) * 8;
                boff[ntp] = (uint32_t)(nr * LDB_S + nk) * 2;
            }

            uint32_t ah[2][4], al[2][4], bh[4][4], bl[4][4];
#pragma unroll
            for (int mt = 0; mt < 2; mt++) ldsm_x4(ah[mt], sAh + aoff[mt]);
#pragma unroll
            for (int ntp = 0; ntp < 4; ntp++) ldsm_x4(bh[ntp], sBh + boff[ntp]);
#pragma unroll
            for (int mt = 0; mt < 2; mt++)
#pragma unroll
                for (int nt = 0; nt < 8; nt++)
                    mma_bf16(acc[mt][nt], ah[mt], &bh[nt >> 1][(nt & 1) * 2]);

#pragma unroll
            for (int mt = 0; mt < 2; mt++) ldsm_x4(al[mt], sAl + aoff[mt]);
#pragma unroll
            for (int mt = 0; mt < 2; mt++)
#pragma unroll
                for (int nt = 0; nt < 8; nt++)
                    mma_bf16(acc[mt][nt], al[mt], &bh[nt >> 1][(nt & 1) * 2]);

#pragma unroll
            for (int ntp = 0; ntp < 4; ntp++) ldsm_x4(bl[ntp], sBl + boff[ntp]);
#pragma unroll
            for (int mt = 0; mt < 2; mt++)
#pragma unroll
                for (int nt = 0; nt < 8; nt++)
                    mma_bf16(acc[mt][nt], ah[mt], &bl[nt >> 1][(nt & 1) * 2]);
        }
        __syncthreads();
    }

    // ---- epilogue: bias + relu ----
#pragma unroll
    for (int mt = 0; mt < 2; mt++) {
        int rbase = row0 + wm * 32 + mt * 16 + g;
#pragma unroll
        for (int nt = 0; nt < 8; nt++) {
            int col = n0 + wn * 64 + nt * 8 + th * 2;
            float bx = bias[col], by = bias[col + 1];
            float2 v0 = make_float2(acc[mt][nt][0] + bx, acc[mt][nt][1] + by);
            float2 v1 = make_float2(acc[mt][nt][2] + bx, acc[mt][nt][3] + by);
            if (do_relu) {
                v0.x = fmaxf(v0.x, 0.f); v0.y = fmaxf(v0.y, 0.f);
                v1.x = fmaxf(v1.x, 0.f); v1.y = fmaxf(v1.y, 0.f);
            }
            if (rbase < M)     *(float2*)(Cc + (size_t)rbase * 256 + col) = v0;
            if (rbase + 8 < M) *(float2*)(Cc + (size_t)(rbase + 8) * 256 + col) = v1;
        }
    }
}

// ---------------- fp32 GEMM (head MLP only; small) ----------------
__global__ __launch_bounds__(256, 2) void gemm_bias_act(
    const float* __restrict__ A1, int K1, const float* __restrict__ B1,
    const float* __restrict__ bias, float* __restrict__ Cc,
    int M, int Nout, int do_relu)
{
    __shared__ float As[8][132];
    __shared__ float Bs[8][128];
    int tid = threadIdx.x;
    int tx = tid & 15, ty = tid >> 4;
    int row0 = blockIdx.x * 128;
    int col0 = blockIdx.y * 128;

    unsigned long long acc[8][4];
#pragma unroll
    for (int i = 0; i < 8; i++)
#pragma unroll
        for (int j = 0; j < 4; j++) acc[i][j] = 0ull;

    int lm = tid >> 1, lk = (tid & 1) * 4;
    int bk = tid >> 5, bn = (tid & 31) * 4;

#pragma unroll 1
    for (int k0 = 0; k0 < K1; k0 += 8) {
        float4 av = make_float4(0.f, 0.f, 0.f, 0.f);
        int r = row0 + lm;
        if (r < M) av = *(const float4*)(A1 + (size_t)r * K1 + k0 + lk);
        float4 bv = *(const float4*)(B1 + (size_t)(k0 + bk) * Nout + col0 + bn);
        __syncthreads();
        As[lk + 0][lm] = av.x; As[lk + 1][lm] = av.y;
        As[lk + 2][lm] = av.z; As[lk + 3][lm] = av.w;
        *(float4*)&Bs[bk][bn] = bv;
        __syncthreads();
#pragma unroll
        for (int k = 0; k < 8; k++) {
            float4 a0 = *(const float4*)&As[k][ty * 4];
            float4 a1 = *(const float4*)&As[k][64 + ty * 4];
            float4 b0 = *(const float4*)&Bs[k][tx * 4];
            float4 b1 = *(const float4*)&Bs[k][64 + tx * 4];
            unsigned long long bp[4];
            bp[0] = pk2(b0.x, b0.y); bp[1] = pk2(b0.z, b0.w);
            bp[2] = pk2(b1.x, b1.y); bp[3] = pk2(b1.z, b1.w);
            float a[8] = {a0.x, a0.y, a0.z, a0.w, a1.x, a1.y, a1.z, a1.w};
#pragma unroll
            for (int i = 0; i < 8; i++) {
                unsigned long long ai = dup2(a[i]);
                fma2(acc[i][0], ai, bp[0]);
                fma2(acc[i][1], ai, bp[1]);
                fma2(acc[i][2], ai, bp[2]);
                fma2(acc[i][3], ai, bp[3]);
            }
        }
    }
#pragma unroll
    for (int i = 0; i < 8; i++) {
        int r = row0 + ((i < 4) ? ty * 4 + i : 64 + ty * 4 + (i - 4));
        if (r >= M) continue;
#pragma unroll
        for (int j = 0; j < 4; j++) {
            int c = col0 + ((j < 2) ? tx * 4 + j * 2 : 64 + tx * 4 + (j - 2) * 2);
            float2 v = upk2(acc[i][j]);
            v.x += bias[c]; v.y += bias[c + 1];
            if (do_relu) { v.x = fmaxf(v.x, 0.f); v.y = fmaxf(v.y, 0.f); }
            *(float2*)(Cc + (size_t)r * Nout + c) = v;
        }
    }
}

// ---------------- global mean pool ----------------
__device__ __forceinline__ int lowerb(const int* __restrict__ a, int n, int key) {
    int lo = 0, hi = n;
    while (lo < hi) { int mid = (lo + hi) >> 1; if (a[mid] < key) lo = mid + 1; else hi = mid; }
    return lo;
}
__global__ void pool_kernel(const float* __restrict__ h, const int* __restrict__ batch,
                            float* __restrict__ pooled) {
    int g = blockIdx.x;
    int c = threadIdx.x;
    __shared__ int s_lo, s_hi;
    if (c == 0) s_lo = lowerb(batch, N_NODES, g);
    if (c == 1) s_hi = lowerb(batch, N_NODES, g + 1);
    __syncthreads();
    int lo = s_lo, hi = s_hi;
    float s = 0.f;
    for (int r = lo; r < hi; r++) s += h[(size_t)r * HID + c];
    float inv = (hi > lo) ? 1.f / (float)(hi - lo) : 0.f;
    pooled[g * HID + c] = s * inv;
}

// ---------------- launch ----------------
extern "C" void kernel_launch(void* const* d_in, const int* in_sizes, int n_in,
                              void* d_out, int out_size) {
    const float* x   = (const float*)d_in[0];
    const int*   ei  = (const int*)d_in[1];
    const int*   src = ei;
    const int*   dst = ei + N_EDGES;
    const int* batch = (const int*)d_in[2];
    const float* W1l = (const float*)d_in[3];
    const float* b1  = (const float*)d_in[4];
    const float* W1r = (const float*)d_in[5];
    const float* W2l = (const float*)d_in[6];
    const float* b2  = (const float*)d_in[7];
    const float* W2r = (const float*)d_in[8];
    const float* W3  = (const float*)d_in[9];
    const float* b3  = (const float*)d_in[10];
    const float* W4  = (const float*)d_in[11];
    const float* b4  = (const float*)d_in[12];
    float* out = (float*)d_out;

    void *p_agg, *p_h1, *p_h2, *p_pool, *p_hidden;
    cudaGetSymbolAddress(&p_agg, g_agg);
    cudaGetSymbolAddress(&p_h1, g_h1);
    cudaGetSymbolAddress(&p_h2, g_h2);
    cudaGetSymbolAddress(&p_pool, g_pool);
    cudaGetSymbolAddress(&p_hidden, g_hidden);
    float* agg    = (float*)p_agg;
    float* h1     = (float*)p_h1;
    float* h2     = (float*)p_h2;
    float* pooled = (float*)p_pool;
    float* hidden = (float*)p_hidden;

    const int TB = 256;
    const dim3 ggrid((N_NODES + 127) / 128, 2);

    // CSR build
    zero_kernel<<<(N_NODES + TB - 1) / TB, TB>>>();
    hist_kernel<<<(N_EDGES + TB - 1) / TB, TB>>>(dst);
    scan_kernel<<<1, 1024>>>();
    scatter_kernel<<<(N_EDGES + TB - 1) / TB, TB>>>(src, dst);

    // Layer 1: h1 = relu([mean-agg(x) | x] @ [W1l;W1r] + b1)
    agg_kernel<IN_CH><<<(N_NODES * 32 + TB - 1) / TB, TB>>>(x, agg);
    hgemm_kernel<<<ggrid, 256>>>(agg, IN_CH, W1l, x, IN_CH, W1r, b1, h1, N_NODES, 1);

    // Layer 2: h2 = relu([mean-agg(h1) | h1] @ [W2l;W2r] + b2)
    agg_kernel<HID><<<(N_NODES * 32 + TB - 1) / TB, TB>>>(h1, agg);
    hgemm_kernel<<<ggrid, 256>>>(agg, HID, W2l, h1, HID, W2r, b2, h2, N_NODES, 1);

    // Pool + MLP head (fp32)
    pool_kernel<<<N_GRAPHS, HID>>>(h2, batch, pooled);
    {
        dim3 grid((N_GRAPHS + 127) / 128, HID / 128);
        gemm_bias_act<<<grid, 256>>>(pooled, HID, W3, b3, hidden, N_GRAPHS, HID, 1);
    }
    {
        dim3 grid((N_GRAPHS + 127) / 128, OUT_CH / 128);
        gemm_bias_act<<<grid, 256>>>(hidden, HID, W4, b4, out, N_GRAPHS, OUT_CH, 0);
    }
}

// round 5
// speedup vs baseline: 1.4855x; 1.1298x over previous
#include <cuda_runtime.h>
#include <cuda_bf16.h>
#include <cstdint>

#define N_NODES  100000
#define N_EDGES  1600000
#define IN_CH    128
#define HID      256
#define OUT_CH   128
#define N_GRAPHS 2048

// ---------------- scratch (device globals: no allocation allowed) ----------------
__device__ int   g_deg[N_NODES];
__device__ int   g_fill[N_NODES];
__device__ int   g_rowptr[N_NODES + 1];
__device__ int   g_col[N_EDGES];
__device__ int   g_part[128];
__device__ int   g_part2[128];
__device__ int   g_gcnt[N_GRAPHS];
__device__ float g_agg[(size_t)N_NODES * HID];
__device__ float g_h1 [(size_t)N_NODES * HID];
__device__ float g_pool  [N_GRAPHS * HID];     // pooled sums, then pooled means (in place)
__device__ float g_hidden[N_GRAPHS * HID];

// ---------------- helpers ----------------
__device__ __forceinline__ uint16_t bf_hi_bits(float v, float& hf) {
    __nv_bfloat16 b = __float2bfloat16_rn(v);
    hf = __bfloat162float(b);
    return *(uint16_t*)&b;
}
__device__ __forceinline__ uint16_t bf_bits(float v) {
    __nv_bfloat16 b = __float2bfloat16_rn(v);
    return *(uint16_t*)&b;
}
__device__ __forceinline__ uint32_t smem_u32(const void* p) {
    uint32_t a;
    asm("{ .reg .u64 t; cvta.to.shared.u64 t, %1; cvt.u32.u64 %0, t; }" : "=r"(a) : "l"(p));
    return a;
}

// packed f32x2 helpers (head MLP GEMM)
__device__ __forceinline__ void fma2(unsigned long long& c, unsigned long long a, unsigned long long b) {
    asm("fma.rn.f32x2 %0, %1, %2, %3;" : "=l"(c) : "l"(a), "l"(b), "l"(c));
}
__device__ __forceinline__ unsigned long long pk2(float lo, float hi) {
    unsigned long long r; asm("mov.b64 %0, {%1, %2};" : "=l"(r) : "f"(lo), "f"(hi)); return r;
}
__device__ __forceinline__ unsigned long long dup2(float x) {
    unsigned long long r; asm("mov.b64 %0, {%1, %1};" : "=l"(r) : "f"(x)); return r;
}
__device__ __forceinline__ float2 upk2(unsigned long long v) {
    float2 r; asm("mov.b64 {%0, %1}, %2;" : "=f"(r.x), "=f"(r.y) : "l"(v)); return r;
}

// ---------------- CSR build + zero ----------------
__global__ void zero_kernel() {
    int i = blockIdx.x * blockDim.x + threadIdx.x;   // grid covers 524288
    if (i < N_NODES) { g_deg[i] = 0; g_fill[i] = 0; }
    if (i < N_GRAPHS * HID) g_pool[i] = 0.f;
    if (i < N_GRAPHS) g_gcnt[i] = 0;
}
__global__ void hist_kernel(const int* __restrict__ dst) {
    int e = blockIdx.x * blockDim.x + threadIdx.x;
    if (e < N_EDGES) atomicAdd(&g_deg[dst[e]], 1);
}
__global__ void bhist_kernel(const int* __restrict__ batch) {
    int i = blockIdx.x * blockDim.x + threadIdx.x;
    if (i < N_NODES) atomicAdd(&g_gcnt[batch[i]], 1);
}
// 3-phase scan of g_deg -> g_rowptr
__global__ void scan1_kernel() {            // 98 CTAs x 1024
    __shared__ int sh[1024];
    int t = threadIdx.x;
    int i = blockIdx.x * 1024 + t;
    sh[t] = (i < N_NODES) ? g_deg[i] : 0;
    __syncthreads();
    for (int off = 512; off > 0; off >>= 1) {
        if (t < off) sh[t] += sh[t + off];
        __syncthreads();
    }
    if (t == 0) g_part[blockIdx.x] = sh[0];
}
__global__ void scan2_kernel(int nparts) {  // 1 CTA x 128
    __shared__ int sh[128];
    int t = threadIdx.x;
    int v = (t < nparts) ? g_part[t] : 0;
    sh[t] = v;
    __syncthreads();
    for (int off = 1; off < 128; off <<= 1) {
        int nv = (t >= off) ? sh[t - off] : 0;
        __syncthreads();
        sh[t] += nv;
        __syncthreads();
    }
    if (t < nparts) g_part2[t] = sh[t] - v;
    if (t == 0) g_rowptr[N_NODES] = N_EDGES;
}
__global__ void scan3_kernel() {            // 98 CTAs x 1024
    __shared__ int sh[1024];
    int t = threadIdx.x;
    int i = blockIdx.x * 1024 + t;
    int v = (i < N_NODES) ? g_deg[i] : 0;
    sh[t] = v;
    __syncthreads();
    for (int off = 1; off < 1024; off <<= 1) {
        int nv = (t >= off) ? sh[t - off] : 0;
        __syncthreads();
        sh[t] += nv;
        __syncthreads();
    }
    if (i < N_NODES) g_rowptr[i] = sh[t] - v + g_part2[blockIdx.x];
}
__global__ void scatter_kernel(const int* __restrict__ src, const int* __restrict__ dst) {
    int e = blockIdx.x * blockDim.x + threadIdx.x;
    if (e >= N_EDGES) return;
    int d = dst[e];
    int p = g_rowptr[d] + atomicAdd(&g_fill[d], 1);
    g_col[p] = src[e];
}

// ---------------- mean aggregation: one warp per node ----------------
template <int C>
__global__ void agg_kernel(const float* __restrict__ feat, float* __restrict__ outp) {
    int w = (blockIdx.x * blockDim.x + threadIdx.x) >> 5;
    int lane = threadIdx.x & 31;
    if (w >= N_NODES) return;
    int beg = g_rowptr[w], end = g_rowptr[w + 1];
    constexpr int V = C / 128;
    float4 acc[V];
#pragma unroll
    for (int v = 0; v < V; v++) acc[v] = make_float4(0.f, 0.f, 0.f, 0.f);
    for (int j = beg; j < end; j++) {
        int s = g_col[j];
        const float4* row = (const float4*)(feat + (size_t)s * C);
#pragma unroll
        for (int v = 0; v < V; v++) {
            float4 t = row[lane + 32 * v];
            acc[v].x += t.x; acc[v].y += t.y; acc[v].z += t.z; acc[v].w += t.w;
        }
    }
    float inv = (end > beg) ? 1.f / (float)(end - beg) : 0.f;
    float4* orow = (float4*)(outp + (size_t)w * C);
#pragma unroll
    for (int v = 0; v < V; v++) {
        acc[v].x *= inv; acc[v].y *= inv; acc[v].z *= inv; acc[v].w *= inv;
        orow[lane + 32 * v] = acc[v];
    }
}

// ---------------- bf16-split HMMA GEMM (ldmatrix + optional fused pool) ----------------
// C[M,256] = relu?( [A1|A2] @ [B1;B2] + bias ),  fp32 in/out.
// 3-pass split: Ahi*Bhi + Alo*Bhi + Ahi*Blo, fp32 accum (mma.sync m16n8k16).
// CTA tile 128x128 (grid.y=2). BK=32. 8 warps = 4(m) x 2(n), warp tile 32x64.
// fuse_pool: instead of storing C, segmented-sum rows by batch[] into psum via atomics.

#define LDB_S 40   // smem row stride in bf16 elems (80B): ldmatrix conflict-free

__device__ __forceinline__ void mma_bf16(float* c, const uint32_t* a, const uint32_t* b) {
    asm volatile(
        "mma.sync.aligned.m16n8k16.row.col.f32.bf16.bf16.f32 "
        "{%0,%1,%2,%3}, {%4,%5,%6,%7}, {%8,%9}, {%0,%1,%2,%3};"
        : "+f"(c[0]), "+f"(c[1]), "+f"(c[2]), "+f"(c[3])
        : "r"(a[0]), "r"(a[1]), "r"(a[2]), "r"(a[3]), "r"(b[0]), "r"(b[1]));
}
__device__ __forceinline__ void ldsm_x4(uint32_t* r, uint32_t addr) {
    asm volatile("ldmatrix.sync.aligned.m8n8.x4.shared.b16 {%0,%1,%2,%3}, [%4];"
                 : "=r"(r[0]), "=r"(r[1]), "=r"(r[2]), "=r"(r[3]) : "r"(addr));
}

__global__ __launch_bounds__(256, 1) void hgemm_kernel(
    const float* __restrict__ A1, int K1, const float* __restrict__ B1,
    const float* __restrict__ A2, int K2, const float* __restrict__ B2,
    const float* __restrict__ bias, float* __restrict__ Cc,
    int M, int do_relu,
    const int* __restrict__ batchp, float* __restrict__ psum, int fuse_pool)
{
    __shared__ __align__(16) uint8_t smraw[40960];
    uint16_t* As_h = (uint16_t*)(smraw);
    uint16_t* As_l = (uint16_t*)(smraw + 10240);
    uint16_t* Bs_h = (uint16_t*)(smraw + 20480);
    uint16_t* Bs_l = (uint16_t*)(smraw + 30720);

    const int tid = threadIdx.x;
    const int lane = tid & 31, wid = tid >> 5;
    const int wm = wid & 3, wn = wid >> 2;          // 4 x 2 warp grid
    const int g = lane >> 2, th = lane & 3;
    const int row0 = blockIdx.x * 128;
    const int n0 = blockIdx.y * 128;

    const uint32_t sAh = smem_u32(smraw);
    const uint32_t sAl = sAh + 10240;
    const uint32_t sBh = sAh + 20480;
    const uint32_t sBl = sAh + 30720;

    const int half1 = K1 >> 5;
    const int nch = half1 + (K2 >> 5);

    float acc[2][8][4];
#pragma unroll
    for (int mt = 0; mt < 2; mt++)
#pragma unroll
        for (int nt = 0; nt < 8; nt++)
#pragma unroll
            for (int r = 0; r < 4; r++) acc[mt][nt][r] = 0.f;

    float4 va[4];
    float  vb[4][4];
    const int lt = lane >> 3, lr = lane & 7;

    // ---- prefetch chunk 0 ----
    {
        const float* Aseg = A1; const float* Bseg = B1; int ldA = K1, kloc = 0;
#pragma unroll
        for (int i = 0; i < 4; i++) {
            int idx = tid + i * 256;
            int r = idx >> 3, q = idx & 7;
            va[i] = (row0 + r < M)
                ? *(const float4*)(Aseg + (size_t)(row0 + r) * ldA + kloc + q * 4)
                : make_float4(0.f, 0.f, 0.f, 0.f);
        }
#pragma unroll
        for (int i = 0; i < 4; i++) {
            int idx = tid + i * 256;
            int n = idx & 127, kq = idx >> 7;
#pragma unroll
            for (int j = 0; j < 4; j++)
                vb[i][j] = Bseg[(size_t)(kloc + kq * 4 + j) * 256 + n0 + n];
        }
    }

#pragma unroll 1
    for (int c = 0; c < nch; c++) {
        // ---- store prefetched chunk to smem (convert + split) ----
#pragma unroll
        for (int i = 0; i < 4; i++) {
            int idx = tid + i * 256;
            int r = idx >> 3, q = idx & 7;
            float f[4] = {va[i].x, va[i].y, va[i].z, va[i].w};
            uint16_t h[4], l[4];
#pragma unroll
            for (int j = 0; j < 4; j++) {
                float hf; h[j] = bf_hi_bits(f[j], hf); l[j] = bf_bits(f[j] - hf);
            }
            uint2 ph = make_uint2((uint32_t)h[0] | ((uint32_t)h[1] << 16),
                                  (uint32_t)h[2] | ((uint32_t)h[3] << 16));
            uint2 pl = make_uint2((uint32_t)l[0] | ((uint32_t)l[1] << 16),
                                  (uint32_t)l[2] | ((uint32_t)l[3] << 16));
            *(uint2*)&As_h[r * LDB_S + q * 4] = ph;
            *(uint2*)&As_l[r * LDB_S + q * 4] = pl;
        }
#pragma unroll
        for (int i = 0; i < 4; i++) {
            int idx = tid + i * 256;
            int n = idx & 127, kq = idx >> 7;
            uint16_t h[4], l[4];
#pragma unroll
            for (int j = 0; j < 4; j++) {
                float hf; h[j] = bf_hi_bits(vb[i][j], hf); l[j] = bf_bits(vb[i][j] - hf);
            }
            uint2 ph = make_uint2((uint32_t)h[0] | ((uint32_t)h[1] << 16),
                                  (uint32_t)h[2] | ((uint32_t)h[3] << 16));
            uint2 pl = make_uint2((uint32_t)l[0] | ((uint32_t)l[1] << 16),
                                  (uint32_t)l[2] | ((uint32_t)l[3] << 16));
            *(uint2*)&Bs_h[n * LDB_S + kq * 4] = ph;
            *(uint2*)&Bs_l[n * LDB_S + kq * 4] = pl;
        }
        __syncthreads();

        // ---- prefetch next chunk ----
        if (c + 1 < nch) {
            int cn = c + 1;
            const float* Aseg; const float* Bseg; int ldA, kloc;
            if (cn < half1) { Aseg = A1; Bseg = B1; ldA = K1; kloc = cn * 32; }
            else            { Aseg = A2; Bseg = B2; ldA = K2; kloc = (cn - half1) * 32; }
#pragma unroll
            for (int i = 0; i < 4; i++) {
                int idx = tid + i * 256;
                int r = idx >> 3, q = idx & 7;
                va[i] = (row0 + r < M)
                    ? *(const float4*)(Aseg + (size_t)(row0 + r) * ldA + kloc + q * 4)
                    : make_float4(0.f, 0.f, 0.f, 0.f);
            }
#pragma unroll
            for (int i = 0; i < 4; i++) {
                int idx = tid + i * 256;
                int n = idx & 127, kq = idx >> 7;
#pragma unroll
                for (int j = 0; j < 4; j++)
                    vb[i][j] = Bseg[(size_t)(kloc + kq * 4 + j) * 256 + n0 + n];
            }
        }

        // ---- compute: 2 k16 steps x 3 passes, ldmatrix fragment loads ----
#pragma unroll
        for (int step = 0; step < 2; step++) {
            const int k0 = step * 16;
            uint32_t aoff[2];
#pragma unroll
            for (int mt = 0; mt < 2; mt++) {
                int ar = wm * 32 + mt * 16 + (lt & 1) * 8 + lr;
                int ak = k0 + (lt >> 1) * 8;
                aoff[mt] = (uint32_t)(ar * LDB_S + ak) * 2;
            }
            uint32_t boff[4];
#pragma unroll
            for (int ntp = 0; ntp < 4; ntp++) {
                int nr = wn * 64 + ntp * 16 + (lt >> 1) * 8 + lr;
                int nk = k0 + (lt & 1) * 8;
                boff[ntp] = (uint32_t)(nr * LDB_S + nk) * 2;
            }

            uint32_t ah[2][4], al[2][4], bh[4][4], bl[4][4];
#pragma unroll
            for (int mt = 0; mt < 2; mt++) ldsm_x4(ah[mt], sAh + aoff[mt]);
#pragma unroll
            for (int ntp = 0; ntp < 4; ntp++) ldsm_x4(bh[ntp], sBh + boff[ntp]);
#pragma unroll
            for (int mt = 0; mt < 2; mt++)
#pragma unroll
                for (int nt = 0; nt < 8; nt++)
                    mma_bf16(acc[mt][nt], ah[mt], &bh[nt >> 1][(nt & 1) * 2]);

#pragma unroll
            for (int mt = 0; mt < 2; mt++) ldsm_x4(al[mt], sAl + aoff[mt]);
#pragma unroll
            for (int mt = 0; mt < 2; mt++)
#pragma unroll
                for (int nt = 0; nt < 8; nt++)
                    mma_bf16(acc[mt][nt], al[mt], &bh[nt >> 1][(nt & 1) * 2]);

#pragma unroll
            for (int ntp = 0; ntp < 4; ntp++) ldsm_x4(bl[ntp], sBl + boff[ntp]);
#pragma unroll
            for (int mt = 0; mt < 2; mt++)
#pragma unroll
                for (int nt = 0; nt < 8; nt++)
                    mma_bf16(acc[mt][nt], ah[mt], &bl[nt >> 1][(nt & 1) * 2]);
        }
        __syncthreads();
    }

    if (!fuse_pool) {
        // ---- epilogue: bias + relu + store ----
#pragma unroll
        for (int mt = 0; mt < 2; mt++) {
            int rbase = row0 + wm * 32 + mt * 16 + g;
#pragma unroll
            for (int nt = 0; nt < 8; nt++) {
                int col = n0 + wn * 64 + nt * 8 + th * 2;
                float bx = bias[col], by = bias[col + 1];
                float2 v0 = make_float2(acc[mt][nt][0] + bx, acc[mt][nt][1] + by);
                float2 v1 = make_float2(acc[mt][nt][2] + bx, acc[mt][nt][3] + by);
                if (do_relu) {
                    v0.x = fmaxf(v0.x, 0.f); v0.y = fmaxf(v0.y, 0.f);
                    v1.x = fmaxf(v1.x, 0.f); v1.y = fmaxf(v1.y, 0.f);
                }
                if (rbase < M)     *(float2*)(Cc + (size_t)rbase * 256 + col) = v0;
                if (rbase + 8 < M) *(float2*)(Cc + (size_t)(rbase + 8) * 256 + col) = v1;
            }
        }
    } else {
        // ---- fused pool epilogue: segmented column sums by batch[] ----
        float* red = (float*)smraw;              // [128][66]
        int*   sbat = (int*)(smraw + 33792);     // [128]
#pragma unroll 1
        for (int h = 0; h < 2; h++) {
            __syncthreads();   // previous half (or mainloop smem) fully consumed
            if (tid < 128) sbat[tid] = (row0 + tid < M) ? batchp[row0 + tid] : -1;
            if (wn == h) {
#pragma unroll
                for (int mt = 0; mt < 2; mt++) {
                    int rl = wm * 32 + mt * 16 + g;
#pragma unroll
                    for (int nt = 0; nt < 8; nt++) {
                        int cl = nt * 8 + th * 2;
                        int colg = n0 + h * 64 + cl;
                        float bx = bias[colg], by = bias[colg + 1];
                        float a0 = fmaxf(acc[mt][nt][0] + bx, 0.f);
                        float a1 = fmaxf(acc[mt][nt][1] + by, 0.f);
                        float a2 = fmaxf(acc[mt][nt][2] + bx, 0.f);
                        float a3 = fmaxf(acc[mt][nt][3] + by, 0.f);
                        red[rl * 66 + cl] = a0;       red[rl * 66 + cl + 1] = a1;
                        red[(rl + 8) * 66 + cl] = a2; red[(rl + 8) * 66 + cl + 1] = a3;
                    }
                }
            }
            __syncthreads();
            int cl = tid & 63, rh = tid >> 6;           // 4 strips of 32 rows
            float run = 0.f; int cur = -1;
#pragma unroll 1
            for (int r = rh * 32; r < rh * 32 + 32; r++) {
                int gb = sbat[r];
                if (gb != cur) {
                    if (cur >= 0)
                        atomicAdd(&psum[(size_t)cur * 256 + n0 + h * 64 + cl], run);
                    run = 0.f; cur = gb;
                }
                if (gb >= 0) run += red[r * 66 + cl];
            }
            if (cur >= 0)
                atomicAdd(&psum[(size_t)cur * 256 + n0 + h * 64 + cl], run);
        }
    }
}

// ---------------- finalize pooled means: psum /= max(cnt,1) (in place) ----------------
__global__ void finalize_kernel() {
    int i = blockIdx.x * blockDim.x + threadIdx.x;
    if (i >= N_GRAPHS * HID) return;
    float c = (float)g_gcnt[i >> 8];
    g_pool[i] = g_pool[i] / fmaxf(c, 1.f);
}

// ---------------- fp32 GEMM (head MLP only; small) ----------------
__global__ __launch_bounds__(256, 2) void gemm_bias_act(
    const float* __restrict__ A1, int K1, const float* __restrict__ B1,
    const float* __restrict__ bias, float* __restrict__ Cc,
    int M, int Nout, int do_relu)
{
    __shared__ float As[8][132];
    __shared__ float Bs[8][128];
    int tid = threadIdx.x;
    int tx = tid & 15, ty = tid >> 4;
    int row0 = blockIdx.x * 128;
    int col0 = blockIdx.y * 128;

    unsigned long long acc[8][4];
#pragma unroll
    for (int i = 0; i < 8; i++)
#pragma unroll
        for (int j = 0; j < 4; j++) acc[i][j] = 0ull;

    int lm = tid >> 1, lk = (tid & 1) * 4;
    int bk = tid >> 5, bn = (tid & 31) * 4;

#pragma unroll 1
    for (int k0 = 0; k0 < K1; k0 += 8) {
        float4 av = make_float4(0.f, 0.f, 0.f, 0.f);
        int r = row0 + lm;
        if (r < M) av = *(const float4*)(A1 + (size_t)r * K1 + k0 + lk);
        float4 bv = *(const float4*)(B1 + (size_t)(k0 + bk) * Nout + col0 + bn);
        __syncthreads();
        As[lk + 0][lm] = av.x; As[lk + 1][lm] = av.y;
        As[lk + 2][lm] = av.z; As[lk + 3][lm] = av.w;
        *(float4*)&Bs[bk][bn] = bv;
        __syncthreads();
#pragma unroll
        for (int k = 0; k < 8; k++) {
            float4 a0 = *(const float4*)&As[k][ty * 4];
            float4 a1 = *(const float4*)&As[k][64 + ty * 4];
            float4 b0 = *(const float4*)&Bs[k][tx * 4];
            float4 b1 = *(const float4*)&Bs[k][64 + tx * 4];
            unsigned long long bp[4];
            bp[0] = pk2(b0.x, b0.y); bp[1] = pk2(b0.z, b0.w);
            bp[2] = pk2(b1.x, b1.y); bp[3] = pk2(b1.z, b1.w);
            float a[8] = {a0.x, a0.y, a0.z, a0.w, a1.x, a1.y, a1.z, a1.w};
#pragma unroll
            for (int i = 0; i < 8; i++) {
                unsigned long long ai = dup2(a[i]);
                fma2(acc[i][0], ai, bp[0]);
                fma2(acc[i][1], ai, bp[1]);
                fma2(acc[i][2], ai, bp[2]);
                fma2(acc[i][3], ai, bp[3]);
            }
        }
    }
#pragma unroll
    for (int i = 0; i < 8; i++) {
        int r = row0 + ((i < 4) ? ty * 4 + i : 64 + ty * 4 + (i - 4));
        if (r >= M) continue;
#pragma unroll
        for (int j = 0; j < 4; j++) {
            int c = col0 + ((j < 2) ? tx * 4 + j * 2 : 64 + tx * 4 + (j - 2) * 2);
            float2 v = upk2(acc[i][j]);
            v.x += bias[c]; v.y += bias[c + 1];
            if (do_relu) { v.x = fmaxf(v.x, 0.f); v.y = fmaxf(v.y, 0.f); }
            *(float2*)(Cc + (size_t)r * Nout + c) = v;
        }
    }
}

// ---------------- launch ----------------
extern "C" void kernel_launch(void* const* d_in, const int* in_sizes, int n_in,
                              void* d_out, int out_size) {
    const float* x   = (const float*)d_in[0];
    const int*   ei  = (const int*)d_in[1];
    const int*   src = ei;
    const int*   dst = ei + N_EDGES;
    const int* batch = (const int*)d_in[2];
    const float* W1l = (const float*)d_in[3];
    const float* b1  = (const float*)d_in[4];
    const float* W1r = (const float*)d_in[5];
    const float* W2l = (const float*)d_in[6];
    const float* b2  = (const float*)d_in[7];
    const float* W2r = (const float*)d_in[8];
    const float* W3  = (const float*)d_in[9];
    const float* b3  = (const float*)d_in[10];
    const float* W4  = (const float*)d_in[11];
    const float* b4  = (const float*)d_in[12];
    float* out = (float*)d_out;

    void *p_agg, *p_h1, *p_pool, *p_hidden;
    cudaGetSymbolAddress(&p_agg, g_agg);
    cudaGetSymbolAddress(&p_h1, g_h1);
    cudaGetSymbolAddress(&p_pool, g_pool);
    cudaGetSymbolAddress(&p_hidden, g_hidden);
    float* agg    = (float*)p_agg;
    float* h1     = (float*)p_h1;
    float* pooled = (float*)p_pool;
    float* hidden = (float*)p_hidden;

    const int TB = 256;
    const dim3 ggrid((N_NODES + 127) / 128, 2);
    const int NSCAN = (N_NODES + 1023) / 1024;   // 98

    // CSR build + zero pooled sums
    zero_kernel<<<(N_GRAPHS * HID + TB - 1) / TB, TB>>>();
    hist_kernel<<<(N_EDGES + TB - 1) / TB, TB>>>(dst);
    bhist_kernel<<<(N_NODES + TB - 1) / TB, TB>>>(batch);
    scan1_kernel<<<NSCAN, 1024>>>();
    scan2_kernel<<<1, 128>>>(NSCAN);
    scan3_kernel<<<NSCAN, 1024>>>();
    scatter_kernel<<<(N_EDGES + TB - 1) / TB, TB>>>(src, dst);

    // Layer 1: h1 = relu([mean-agg(x) | x] @ [W1l;W1r] + b1)
    agg_kernel<IN_CH><<<(N_NODES * 32 + TB - 1) / TB, TB>>>(x, agg);
    hgemm_kernel<<<ggrid, 256>>>(agg, IN_CH, W1l, x, IN_CH, W1r, b1, h1, N_NODES, 1,
                                 nullptr, nullptr, 0);

    // Layer 2 + fused pool: psum += segsum(relu([agg|h1] @ [W2l;W2r] + b2))
    agg_kernel<HID><<<(N_NODES * 32 + TB - 1) / TB, TB>>>(h1, agg);
    hgemm_kernel<<<ggrid, 256>>>(agg, HID, W2l, h1, HID, W2r, b2, nullptr, N_NODES, 1,
                                 batch, pooled, 1);

    // pooled means
    finalize_kernel<<<(N_GRAPHS * HID + TB - 1) / TB, TB>>>();

    // MLP head (fp32)
    {
        dim3 grid((N_GRAPHS + 127) / 128, HID / 128);
        gemm_bias_act<<<grid, 256>>>(pooled, HID, W3, b3, hidden, N_GRAPHS, HID, 1);
    }
    {
        dim3 grid((N_GRAPHS + 127) / 128, OUT_CH / 128);
        gemm_bias_act<<<grid, 256>>>(hidden, HID, W4, b4, out, N_GRAPHS, OUT_CH, 0);
    }
}

// round 6
// speedup vs baseline: 1.5210x; 1.0239x over previous
#include <cuda_runtime.h>
#include <cuda_bf16.h>
#include <cstdint>

#define N_NODES  100000
#define N_EDGES  1600000
#define IN_CH    128
#define HID      256
#define OUT_CH   128
#define N_GRAPHS 2048

// ---------------- scratch (device globals: no allocation allowed) ----------------
__device__ int   g_deg[N_NODES];
__device__ int   g_fill[N_NODES];
__device__ int   g_rowptr[N_NODES + 1];
__device__ int   g_col[N_EDGES];
__device__ int   g_part[128];
__device__ int   g_part2[128];
__device__ int   g_gcnt[N_GRAPHS];
__device__ uint16_t g_Ah[(size_t)N_NODES * 512];   // bf16 hi operand panel (stride 512)
__device__ uint16_t g_Al[(size_t)N_NODES * 512];   // bf16 lo operand panel
__device__ uint16_t g_B1h[256 * 512], g_B1l[256 * 512];
__device__ uint16_t g_B2h[256 * 512], g_B2l[256 * 512];
__device__ float g_h1 [(size_t)N_NODES * HID];
__device__ float g_pool  [N_GRAPHS * HID];
__device__ float g_hidden[N_GRAPHS * HID];

// ---------------- helpers ----------------
__device__ __forceinline__ uint16_t bf_hi_bits(float v, float& hf) {
    __nv_bfloat16 b = __float2bfloat16_rn(v);
    hf = __bfloat162float(b);
    return *(uint16_t*)&b;
}
__device__ __forceinline__ uint16_t bf_bits(float v) {
    __nv_bfloat16 b = __float2bfloat16_rn(v);
    return *(uint16_t*)&b;
}
__device__ __forceinline__ uint32_t smem_u32(const void* p) {
    uint32_t a;
    asm("{ .reg .u64 t; cvta.to.shared.u64 t, %1; cvt.u32.u64 %0, t; }" : "=r"(a) : "l"(p));
    return a;
}

// packed f32x2 helpers (head MLP GEMM)
__device__ __forceinline__ void fma2(unsigned long long& c, unsigned long long a, unsigned long long b) {
    asm("fma.rn.f32x2 %0, %1, %2, %3;" : "=l"(c) : "l"(a), "l"(b), "l"(c));
}
__device__ __forceinline__ unsigned long long pk2(float lo, float hi) {
    unsigned long long r; asm("mov.b64 %0, {%1, %2};" : "=l"(r) : "f"(lo), "f"(hi)); return r;
}
__device__ __forceinline__ unsigned long long dup2(float x) {
    unsigned long long r; asm("mov.b64 %0, {%1, %1};" : "=l"(r) : "f"(x)); return r;
}
__device__ __forceinline__ float2 upk2(unsigned long long v) {
    float2 r; asm("mov.b64 {%0, %1}, %2;" : "=f"(r.x), "=f"(r.y) : "l"(v)); return r;
}

// ---------------- CSR build + zero ----------------
__global__ void zero_kernel() {
    int i = blockIdx.x * blockDim.x + threadIdx.x;   // grid covers 524288
    if (i < N_NODES) { g_deg[i] = 0; g_fill[i] = 0; }
    if (i < N_GRAPHS * HID) g_pool[i] = 0.f;
    if (i < N_GRAPHS) g_gcnt[i] = 0;
}
__global__ void hist_kernel(const int* __restrict__ dst, const int* __restrict__ batch) {
    int e = blockIdx.x * blockDim.x + threadIdx.x;
    if (e < N_EDGES) atomicAdd(&g_deg[dst[e]], 1);
    if (e < N_NODES) atomicAdd(&g_gcnt[batch[e]], 1);
}
__global__ void scan1_kernel() {
    __shared__ int sh[1024];
    int t = threadIdx.x;
    int i = blockIdx.x * 1024 + t;
    sh[t] = (i < N_NODES) ? g_deg[i] : 0;
    __syncthreads();
    for (int off = 512; off > 0; off >>= 1) {
        if (t < off) sh[t] += sh[t + off];
        __syncthreads();
    }
    if (t == 0) g_part[blockIdx.x] = sh[0];
}
__global__ void scan2_kernel(int nparts) {
    __shared__ int sh[128];
    int t = threadIdx.x;
    int v = (t < nparts) ? g_part[t] : 0;
    sh[t] = v;
    __syncthreads();
    for (int off = 1; off < 128; off <<= 1) {
        int nv = (t >= off) ? sh[t - off] : 0;
        __syncthreads();
        sh[t] += nv;
        __syncthreads();
    }
    if (t < nparts) g_part2[t] = sh[t] - v;
    if (t == 0) g_rowptr[N_NODES] = N_EDGES;
}
__global__ void scan3_kernel() {
    __shared__ int sh[1024];
    int t = threadIdx.x;
    int i = blockIdx.x * 1024 + t;
    int v = (i < N_NODES) ? g_deg[i] : 0;
    sh[t] = v;
    __syncthreads();
    for (int off = 1; off < 1024; off <<= 1) {
        int nv = (t >= off) ? sh[t - off] : 0;
        __syncthreads();
        sh[t] += nv;
        __syncthreads();
    }
    if (i < N_NODES) g_rowptr[i] = sh[t] - v + g_part2[blockIdx.x];
}
__global__ void scatter_kernel(const int* __restrict__ src, const int* __restrict__ dst) {
    int e = blockIdx.x * blockDim.x + threadIdx.x;
    if (e >= N_EDGES) return;
    int d = dst[e];
    int p = g_rowptr[d] + atomicAdd(&g_fill[d], 1);
    g_col[p] = src[e];
}

// ---------------- split writers ----------------
__device__ __forceinline__ void split_store4(uint16_t* Ah, uint16_t* Al, size_t base,
                                             float v0, float v1, float v2, float v3) {
    float hf0, hf1, hf2, hf3;
    uint16_t h0 = bf_hi_bits(v0, hf0), h1 = bf_hi_bits(v1, hf1);
    uint16_t h2 = bf_hi_bits(v2, hf2), h3 = bf_hi_bits(v3, hf3);
    uint16_t l0 = bf_bits(v0 - hf0), l1 = bf_bits(v1 - hf1);
    uint16_t l2 = bf_bits(v2 - hf2), l3 = bf_bits(v3 - hf3);
    *(uint2*)(Ah + base) = make_uint2((uint32_t)h0 | ((uint32_t)h1 << 16),
                                      (uint32_t)h2 | ((uint32_t)h3 << 16));
    *(uint2*)(Al + base) = make_uint2((uint32_t)l0 | ((uint32_t)l1 << 16),
                                      (uint32_t)l2 | ((uint32_t)l3 << 16));
}

// mean aggregation (one warp per node) with fused split; writes A panel cols 0..C-1
template <int C>
__global__ void agg_split_kernel(const float* __restrict__ feat,
                                 uint16_t* __restrict__ Ah, uint16_t* __restrict__ Al) {
    int w = (blockIdx.x * blockDim.x + threadIdx.x) >> 5;
    int lane = threadIdx.x & 31;
    if (w >= N_NODES) return;
    int beg = g_rowptr[w], end = g_rowptr[w + 1];
    constexpr int V = C / 128;
    float4 acc[V];
#pragma unroll
    for (int v = 0; v < V; v++) acc[v] = make_float4(0.f, 0.f, 0.f, 0.f);
    for (int j = beg; j < end; j++) {
        int s = g_col[j];
        const float4* row = (const float4*)(feat + (size_t)s * C);
#pragma unroll
        for (int v = 0; v < V; v++) {
            float4 t = row[lane + 32 * v];
            acc[v].x += t.x; acc[v].y += t.y; acc[v].z += t.z; acc[v].w += t.w;
        }
    }
    float inv = (end > beg) ? 1.f / (float)(end - beg) : 0.f;
#pragma unroll
    for (int v = 0; v < V; v++) {
        size_t base = (size_t)w * 512 + (size_t)(lane + 32 * v) * 4;
        split_store4(Ah, Al, base, acc[v].x * inv, acc[v].y * inv, acc[v].z * inv, acc[v].w * inv);
    }
}

// split x (fp32 [N,128]) into A panel cols 128..255
__global__ void xsplit_kernel(const float* __restrict__ x,
                              uint16_t* __restrict__ Ah, uint16_t* __restrict__ Al) {
    int idx = blockIdx.x * blockDim.x + threadIdx.x;     // N_NODES*32 float4
    if (idx >= N_NODES * 32) return;
    int row = idx >> 5, q = idx & 31;
    float4 v = ((const float4*)x)[idx];
    split_store4(Ah, Al, (size_t)row * 512 + 128 + (size_t)q * 4, v.x, v.y, v.z, v.w);
}

// transpose + split weight W[Kw,256] into B panel: B[n*512 + cofs + k]
__global__ void wsplit_kernel(const float* __restrict__ W, int Kw, int cofs,
                              uint16_t* __restrict__ Bh, uint16_t* __restrict__ Bl) {
    int idx = blockIdx.x * blockDim.x + threadIdx.x;
    if (idx >= 256 * Kw) return;
    int n = idx / Kw, k = idx - n * Kw;
    float v = W[(size_t)k * 256 + n];
    float hf; uint16_t h = bf_hi_bits(v, hf);
    Bh[(size_t)n * 512 + cofs + k] = h;
    Bl[(size_t)n * 512 + cofs + k] = bf_bits(v - hf);
}

// ---------------- pre-split bf16 HMMA GEMM ----------------
// C[M,256] = relu( A @ B^T + bias ) with A = hi+lo panels (stride 512), B likewise.
// 3-pass split: Ahi*Bhi + Alo*Bhi + Ahi*Blo. CTA tile 128x128 (grid.y=2), BK=32.
// Optionally writes split C into oAh/oAl cols 256.. ; optionally fused pool epilogue.

#define LDB_S 40

__device__ __forceinline__ void mma_bf16(float* c, const uint32_t* a, const uint32_t* b) {
    asm volatile(
        "mma.sync.aligned.m16n8k16.row.col.f32.bf16.bf16.f32 "
        "{%0,%1,%2,%3}, {%4,%5,%6,%7}, {%8,%9}, {%0,%1,%2,%3};"
        : "+f"(c[0]), "+f"(c[1]), "+f"(c[2]), "+f"(c[3])
        : "r"(a[0]), "r"(a[1]), "r"(a[2]), "r"(a[3]), "r"(b[0]), "r"(b[1]));
}
__device__ __forceinline__ void ldsm_x4(uint32_t* r, uint32_t addr) {
    asm volatile("ldmatrix.sync.aligned.m8n8.x4.shared.b16 {%0,%1,%2,%3}, [%4];"
                 : "=r"(r[0]), "=r"(r[1]), "=r"(r[2]), "=r"(r[3]) : "r"(addr));
}

__global__ __launch_bounds__(256, 1) void hgemm_kernel(
    const uint16_t* __restrict__ Ah, const uint16_t* __restrict__ Al,
    const uint16_t* __restrict__ Bh, const uint16_t* __restrict__ Bl,
    int K, const float* __restrict__ bias, float* __restrict__ Cc,
    uint16_t* __restrict__ oAh, uint16_t* __restrict__ oAl,
    int M, const int* __restrict__ batchp, float* __restrict__ psum, int fuse_pool)
{
    __shared__ __align__(16) uint8_t smraw[40960];
    uint16_t* As_h = (uint16_t*)(smraw);
    uint16_t* As_l = (uint16_t*)(smraw + 10240);
    uint16_t* Bs_h = (uint16_t*)(smraw + 20480);
    uint16_t* Bs_l = (uint16_t*)(smraw + 30720);

    const int tid = threadIdx.x;
    const int lane = tid & 31, wid = tid >> 5;
    const int wm = wid & 3, wn = wid >> 2;
    const int g = lane >> 2, th = lane & 3;
    const int row0 = blockIdx.x * 128;
    const int n0 = blockIdx.y * 128;

    const uint32_t sAh = smem_u32(smraw);
    const uint32_t sAl = sAh + 10240;
    const uint32_t sBh = sAh + 20480;
    const uint32_t sBl = sAh + 30720;

    const int nch = K >> 5;

    float acc[2][8][4];
#pragma unroll
    for (int mt = 0; mt < 2; mt++)
#pragma unroll
        for (int nt = 0; nt < 8; nt++)
#pragma unroll
            for (int r = 0; r < 4; r++) acc[mt][nt][r] = 0.f;

    const int lt = lane >> 3, lr = lane & 7;
    const int pr = tid >> 2, pq = tid & 3;      // loader: row 0..63(+64), 16B-unit in 32-elem row

    uint4 ra_h[2], ra_l[2], rb_h[2], rb_l[2];

    // ---- prefetch chunk 0 ----
    {
#pragma unroll
        for (int i = 0; i < 2; i++) {
            int r = pr + i * 64;
            int ga = row0 + r;
            size_t ao = (size_t)ga * 512 + pq * 8;
            if (ga < M) { ra_h[i] = *(const uint4*)(Ah + ao); ra_l[i] = *(const uint4*)(Al + ao); }
            else        { ra_h[i] = make_uint4(0,0,0,0);      ra_l[i] = make_uint4(0,0,0,0); }
            size_t bo = (size_t)(n0 + r) * 512 + pq * 8;
            rb_h[i] = *(const uint4*)(Bh + bo);
            rb_l[i] = *(const uint4*)(Bl + bo);
        }
    }

#pragma unroll 1
    for (int c = 0; c < nch; c++) {
        // ---- store prefetched chunk to smem ----
#pragma unroll
        for (int i = 0; i < 2; i++) {
            int r = pr + i * 64;
            int so = r * LDB_S + pq * 8;
            *(uint4*)&As_h[so] = ra_h[i];
            *(uint4*)&As_l[so] = ra_l[i];
            *(uint4*)&Bs_h[so] = rb_h[i];
            *(uint4*)&Bs_l[so] = rb_l[i];
        }
        __syncthreads();

        // ---- prefetch next chunk ----
        if (c + 1 < nch) {
            int kb = (c + 1) * 32;
#pragma unroll
            for (int i = 0; i < 2; i++) {
                int r = pr + i * 64;
                int ga = row0 + r;
                size_t ao = (size_t)ga * 512 + kb + pq * 8;
                if (ga < M) { ra_h[i] = *(const uint4*)(Ah + ao); ra_l[i] = *(const uint4*)(Al + ao); }
                else        { ra_h[i] = make_uint4(0,0,0,0);      ra_l[i] = make_uint4(0,0,0,0); }
                size_t bo = (size_t)(n0 + r) * 512 + kb + pq * 8;
                rb_h[i] = *(const uint4*)(Bh + bo);
                rb_l[i] = *(const uint4*)(Bl + bo);
            }
        }

        // ---- compute: 2 k16 steps x 3 passes ----
#pragma unroll
        for (int step = 0; step < 2; step++) {
            const int k0 = step * 16;
            uint32_t aoff[2];
#pragma unroll
            for (int mt = 0; mt < 2; mt++) {
                int ar = wm * 32 + mt * 16 + (lt & 1) * 8 + lr;
                int ak = k0 + (lt >> 1) * 8;
                aoff[mt] = (uint32_t)(ar * LDB_S + ak) * 2;
            }
            uint32_t boff[4];
#pragma unroll
            for (int ntp = 0; ntp < 4; ntp++) {
                int nr = wn * 64 + ntp * 16 + (lt >> 1) * 8 + lr;
                int nk = k0 + (lt & 1) * 8;
                boff[ntp] = (uint32_t)(nr * LDB_S + nk) * 2;
            }

            uint32_t ah[2][4], al[2][4], bh[4][4], bl[4][4];
#pragma unroll
            for (int mt = 0; mt < 2; mt++) ldsm_x4(ah[mt], sAh + aoff[mt]);
#pragma unroll
            for (int ntp = 0; ntp < 4; ntp++) ldsm_x4(bh[ntp], sBh + boff[ntp]);
#pragma unroll
            for (int mt = 0; mt < 2; mt++)
#pragma unroll
                for (int nt = 0; nt < 8; nt++)
                    mma_bf16(acc[mt][nt], ah[mt], &bh[nt >> 1][(nt & 1) * 2]);

#pragma unroll
            for (int mt = 0; mt < 2; mt++) ldsm_x4(al[mt], sAl + aoff[mt]);
#pragma unroll
            for (int mt = 0; mt < 2; mt++)
#pragma unroll
                for (int nt = 0; nt < 8; nt++)
                    mma_bf16(acc[mt][nt], al[mt], &bh[nt >> 1][(nt & 1) * 2]);

#pragma unroll
            for (int ntp = 0; ntp < 4; ntp++) ldsm_x4(bl[ntp], sBl + boff[ntp]);
#pragma unroll
            for (int mt = 0; mt < 2; mt++)
#pragma unroll
                for (int nt = 0; nt < 8; nt++)
                    mma_bf16(acc[mt][nt], ah[mt], &bl[nt >> 1][(nt & 1) * 2]);
        }
        __syncthreads();
    }

    if (!fuse_pool) {
        // ---- epilogue: bias + relu + fp32 store + split store ----
#pragma unroll
        for (int mt = 0; mt < 2; mt++) {
            int rbase = row0 + wm * 32 + mt * 16 + g;
#pragma unroll
            for (int nt = 0; nt < 8; nt++) {
                int col = n0 + wn * 64 + nt * 8 + th * 2;
                float bx = bias[col], by = bias[col + 1];
                float2 v0 = make_float2(fmaxf(acc[mt][nt][0] + bx, 0.f),
                                        fmaxf(acc[mt][nt][1] + by, 0.f));
                float2 v1 = make_float2(fmaxf(acc[mt][nt][2] + bx, 0.f),
                                        fmaxf(acc[mt][nt][3] + by, 0.f));
                if (rbase < M) {
                    *(float2*)(Cc + (size_t)rbase * 256 + col) = v0;
                    float hf0, hf1;
                    uint16_t h0 = bf_hi_bits(v0.x, hf0), h1 = bf_hi_bits(v0.y, hf1);
                    uint16_t l0 = bf_bits(v0.x - hf0),   l1 = bf_bits(v0.y - hf1);
                    size_t ob = (size_t)rbase * 512 + 256 + col;
                    *(uint32_t*)(oAh + ob) = (uint32_t)h0 | ((uint32_t)h1 << 16);
                    *(uint32_t*)(oAl + ob) = (uint32_t)l0 | ((uint32_t)l1 << 16);
                }
                if (rbase + 8 < M) {
                    *(float2*)(Cc + (size_t)(rbase + 8) * 256 + col) = v1;
                    float hf0, hf1;
                    uint16_t h0 = bf_hi_bits(v1.x, hf0), h1 = bf_hi_bits(v1.y, hf1);
                    uint16_t l0 = bf_bits(v1.x - hf0),   l1 = bf_bits(v1.y - hf1);
                    size_t ob = (size_t)(rbase + 8) * 512 + 256 + col;
                    *(uint32_t*)(oAh + ob) = (uint32_t)h0 | ((uint32_t)h1 << 16);
                    *(uint32_t*)(oAl + ob) = (uint32_t)l0 | ((uint32_t)l1 << 16);
                }
            }
        }
    } else {
        // ---- fused pool epilogue: segmented column sums by batch[] ----
        float* red = (float*)smraw;              // [128][66]
        int*   sbat = (int*)(smraw + 33792);     // [128]
#pragma unroll 1
        for (int h = 0; h < 2; h++) {
            __syncthreads();
            if (tid < 128) sbat[tid] = (row0 + tid < M) ? batchp[row0 + tid] : -1;
            if (wn == h) {
#pragma unroll
                for (int mt = 0; mt < 2; mt++) {
                    int rl = wm * 32 + mt * 16 + g;
#pragma unroll
                    for (int nt = 0; nt < 8; nt++) {
                        int cl = nt * 8 + th * 2;
                        int colg = n0 + h * 64 + cl;
                        float bx = bias[colg], by = bias[colg + 1];
                        red[rl * 66 + cl]       = fmaxf(acc[mt][nt][0] + bx, 0.f);
                        red[rl * 66 + cl + 1]   = fmaxf(acc[mt][nt][1] + by, 0.f);
                        red[(rl + 8) * 66 + cl]     = fmaxf(acc[mt][nt][2] + bx, 0.f);
                        red[(rl + 8) * 66 + cl + 1] = fmaxf(acc[mt][nt][3] + by, 0.f);
                    }
                }
            }
            __syncthreads();
            int cl = tid & 63, rh = tid >> 6;
            float run = 0.f; int cur = -1;
#pragma unroll 1
            for (int r = rh * 32; r < rh * 32 + 32; r++) {
                int gb = sbat[r];
                if (gb != cur) {
                    if (cur >= 0)
                        atomicAdd(&psum[(size_t)cur * 256 + n0 + h * 64 + cl], run);
                    run = 0.f; cur = gb;
                }
                if (gb >= 0) run += red[r * 66 + cl];
            }
            if (cur >= 0)
                atomicAdd(&psum[(size_t)cur * 256 + n0 + h * 64 + cl], run);
        }
    }
}

// ---------------- finalize pooled means ----------------
__global__ void finalize_kernel() {
    int i = blockIdx.x * blockDim.x + threadIdx.x;
    if (i >= N_GRAPHS * HID) return;
    float c = (float)g_gcnt[i >> 8];
    g_pool[i] = g_pool[i] / fmaxf(c, 1.f);
}

// ---------------- fp32 GEMM (head MLP only; small) ----------------
__global__ __launch_bounds__(256, 2) void gemm_bias_act(
    const float* __restrict__ A1, int K1, const float* __restrict__ B1,
    const float* __restrict__ bias, float* __restrict__ Cc,
    int M, int Nout, int do_relu)
{
    __shared__ float As[8][132];
    __shared__ float Bs[8][128];
    int tid = threadIdx.x;
    int tx = tid & 15, ty = tid >> 4;
    int row0 = blockIdx.x * 128;
    int col0 = blockIdx.y * 128;

    unsigned long long acc[8][4];
#pragma unroll
    for (int i = 0; i < 8; i++)
#pragma unroll
        for (int j = 0; j < 4; j++) acc[i][j] = 0ull;

    int lm = tid >> 1, lk = (tid & 1) * 4;
    int bk = tid >> 5, bn = (tid & 31) * 4;

#pragma unroll 1
    for (int k0 = 0; k0 < K1; k0 += 8) {
        float4 av = make_float4(0.f, 0.f, 0.f, 0.f);
        int r = row0 + lm;
        if (r < M) av = *(const float4*)(A1 + (size_t)r * K1 + k0 + lk);
        float4 bv = *(const float4*)(B1 + (size_t)(k0 + bk) * Nout + col0 + bn);
        __syncthreads();
        As[lk + 0][lm] = av.x; As[lk + 1][lm] = av.y;
        As[lk + 2][lm] = av.z; As[lk + 3][lm] = av.w;
        *(float4*)&Bs[bk][bn] = bv;
        __syncthreads();
#pragma unroll
        for (int k = 0; k < 8; k++) {
            float4 a0 = *(const float4*)&As[k][ty * 4];
            float4 a1 = *(const float4*)&As[k][64 + ty * 4];
            float4 b0 = *(const float4*)&Bs[k][tx * 4];
            float4 b1 = *(const float4*)&Bs[k][64 + tx * 4];
            unsigned long long bp[4];
            bp[0] = pk2(b0.x, b0.y); bp[1] = pk2(b0.z, b0.w);
            bp[2] = pk2(b1.x, b1.y); bp[3] = pk2(b1.z, b1.w);
            float a[8] = {a0.x, a0.y, a0.z, a0.w, a1.x, a1.y, a1.z, a1.w};
#pragma unroll
            for (int i = 0; i < 8; i++) {
                unsigned long long ai = dup2(a[i]);
                fma2(acc[i][0], ai, bp[0]);
                fma2(acc[i][1], ai, bp[1]);
                fma2(acc[i][2], ai, bp[2]);
                fma2(acc[i][3], ai, bp[3]);
            }
        }
    }
#pragma unroll
    for (int i = 0; i < 8; i++) {
        int r = row0 + ((i < 4) ? ty * 4 + i : 64 + ty * 4 + (i - 4));
        if (r >= M) continue;
#pragma unroll
        for (int j = 0; j < 4; j++) {
            int c = col0 + ((j < 2) ? tx * 4 + j * 2 : 64 + tx * 4 + (j - 2) * 2);
            float2 v = upk2(acc[i][j]);
            v.x += bias[c]; v.y += bias[c + 1];
            if (do_relu) { v.x = fmaxf(v.x, 0.f); v.y = fmaxf(v.y, 0.f); }
            *(float2*)(Cc + (size_t)r * Nout + c) = v;
        }
    }
}

// ---------------- launch ----------------
extern "C" void kernel_launch(void* const* d_in, const int* in_sizes, int n_in,
                              void* d_out, int out_size) {
    const float* x   = (const float*)d_in[0];
    const int*   ei  = (const int*)d_in[1];
    const int*   src = ei;
    const int*   dst = ei + N_EDGES;
    const int* batch = (const int*)d_in[2];
    const float* W1l = (const float*)d_in[3];
    const float* b1  = (const float*)d_in[4];
    const float* W1r = (const float*)d_in[5];
    const float* W2l = (const float*)d_in[6];
    const float* b2  = (const float*)d_in[7];
    const float* W2r = (const float*)d_in[8];
    const float* W3  = (const float*)d_in[9];
    const float* b3  = (const float*)d_in[10];
    const float* W4  = (const float*)d_in[11];
    const float* b4  = (const float*)d_in[12];
    float* out = (float*)d_out;

    void *p_h1, *p_pool, *p_hidden, *p_Ah, *p_Al, *p_B1h, *p_B1l, *p_B2h, *p_B2l;
    cudaGetSymbolAddress(&p_h1, g_h1);
    cudaGetSymbolAddress(&p_pool, g_pool);
    cudaGetSymbolAddress(&p_hidden, g_hidden);
    cudaGetSymbolAddress(&p_Ah, g_Ah);
    cudaGetSymbolAddress(&p_Al, g_Al);
    cudaGetSymbolAddress(&p_B1h, g_B1h);
    cudaGetSymbolAddress(&p_B1l, g_B1l);
    cudaGetSymbolAddress(&p_B2h, g_B2h);
    cudaGetSymbolAddress(&p_B2l, g_B2l);
    float* h1 = (float*)p_h1;
    float* pooled = (float*)p_pool;
    float* hidden = (float*)p_hidden;
    uint16_t* Ah = (uint16_t*)p_Ah;
    uint16_t* Al = (uint16_t*)p_Al;
    uint16_t* B1h = (uint16_t*)p_B1h;
    uint16_t* B1l = (uint16_t*)p_B1l;
    uint16_t* B2h = (uint16_t*)p_B2h;
    uint16_t* B2l = (uint16_t*)p_B2l;

    const int TB = 256;
    const dim3 ggrid((N_NODES + 127) / 128, 2);
    const int NSCAN = (N_NODES + 1023) / 1024;

    // CSR build + zero pooled sums
    zero_kernel<<<(N_GRAPHS * HID + TB - 1) / TB, TB>>>();
    hist_kernel<<<(N_EDGES + TB - 1) / TB, TB>>>(dst, batch);
    scan1_kernel<<<NSCAN, 1024>>>();
    scan2_kernel<<<1, 128>>>(NSCAN);
    scan3_kernel<<<NSCAN, 1024>>>();
    scatter_kernel<<<(N_EDGES + TB - 1) / TB, TB>>>(src, dst);

    // one-shot weight + x splits
    wsplit_kernel<<<(256 * 128 + TB - 1) / TB, TB>>>(W1l, 128, 0, B1h, B1l);
    wsplit_kernel<<<(256 * 128 + TB - 1) / TB, TB>>>(W1r, 128, 128, B1h, B1l);
    wsplit_kernel<<<(256 * 256 + TB - 1) / TB, TB>>>(W2l, 256, 0, B2h, B2l);
    wsplit_kernel<<<(256 * 256 + TB - 1) / TB, TB>>>(W2r, 256, 256, B2h, B2l);
    xsplit_kernel<<<(N_NODES * 32 + TB - 1) / TB, TB>>>(x, Ah, Al);

    // Layer 1: A panel = [split agg(x) | split x], K=256
    agg_split_kernel<IN_CH><<<(N_NODES * 32 + TB - 1) / TB, TB>>>(x, Ah, Al);
    hgemm_kernel<<<ggrid, 256>>>(Ah, Al, B1h, B1l, 256, b1, h1, Ah, Al, N_NODES,
                                 nullptr, nullptr, 0);   // also splits h1 -> cols 256..511

    // Layer 2: A panel = [split agg(h1) | split h1], K=512; fused pool
    agg_split_kernel<HID><<<(N_NODES * 32 + TB - 1) / TB, TB>>>(h1, Ah, Al);
    hgemm_kernel<<<ggrid, 256>>>(Ah, Al, B2h, B2l, 512, b2, nullptr, nullptr, nullptr,
                                 N_NODES, batch, pooled, 1);

    // pooled means + MLP head
    finalize_kernel<<<(N_GRAPHS * HID + TB - 1) / TB, TB>>>();
    {
        dim3 grid((N_GRAPHS + 127) / 128, HID / 128);
        gemm_bias_act<<<grid, 256>>>(pooled, HID, W3, b3, hidden, N_GRAPHS, HID, 1);
    }
    {
        dim3 grid((N_GRAPHS + 127) / 128, OUT_CH / 128);
        gemm_bias_act<<<grid, 256>>>(hidden, HID, W4, b4, out, N_GRAPHS, OUT_CH, 0);
    }
}